// round 7
// baseline (speedup 1.0000x reference)
#include <cuda_runtime.h>
#include <cuda_bf16.h>
#include <cstdint>

#define D_MODEL 2048
#define HIDDEN 1024
#define NUM_EXPERTS 8
#define TPE 2048
#define TOTAL_TOKENS 16384

// bf16 hi/lo pre-split copies (written once per launch by split kernels)
__device__ __nv_bfloat16 g_x_hi[(size_t)TOTAL_TOKENS * D_MODEL];
__device__ __nv_bfloat16 g_x_lo[(size_t)TOTAL_TOKENS * D_MODEL];
__device__ __nv_bfloat16 g_wug_hi[(size_t)2 * NUM_EXPERTS * HIDDEN * D_MODEL];
__device__ __nv_bfloat16 g_wug_lo[(size_t)2 * NUM_EXPERTS * HIDDEN * D_MODEL];
__device__ __nv_bfloat16 g_wd_hi[(size_t)D_MODEL * NUM_EXPERTS * HIDDEN];
__device__ __nv_bfloat16 g_wd_lo[(size_t)D_MODEL * NUM_EXPERTS * HIDDEN];
__device__ __nv_bfloat16 g_h_hi[(size_t)TOTAL_TOKENS * HIDDEN];
__device__ __nv_bfloat16 g_h_lo[(size_t)TOTAL_TOKENS * HIDDEN];

// ---------------- helpers ----------------
// 32B rows; toggle 16B half by row bit2 -> conflict-free ldmatrix & STS
__device__ __forceinline__ uint32_t SW(uint32_t off) {
    return off ^ (((off >> 7) & 1u) << 4);
}

__device__ __forceinline__ uint32_t smem_u32(const void* p) {
    return (uint32_t)__cvta_generic_to_shared(p);
}

__device__ __forceinline__ void mma_bf16(float* c, const uint32_t* a,
                                         uint32_t b0, uint32_t b1) {
    asm volatile(
        "mma.sync.aligned.m16n8k16.row.col.f32.bf16.bf16.f32 "
        "{%0,%1,%2,%3}, {%4,%5,%6,%7}, {%8,%9}, {%0,%1,%2,%3};"
        : "+f"(c[0]), "+f"(c[1]), "+f"(c[2]), "+f"(c[3])
        : "r"(a[0]), "r"(a[1]), "r"(a[2]), "r"(a[3]), "r"(b0), "r"(b1));
}

__device__ __forceinline__ void ldsm4(uint32_t r[4], uint32_t saddr) {
    asm volatile("ldmatrix.sync.aligned.m8n8.x4.shared.b16 {%0,%1,%2,%3}, [%4];"
                 : "=r"(r[0]), "=r"(r[1]), "=r"(r[2]), "=r"(r[3]) : "r"(saddr));
}

#define CP_ASYNC16(dst, src) \
    asm volatile("cp.async.cg.shared.global [%0], [%1], 16;" :: "r"(dst), "l"(src))
#define CP_COMMIT() asm volatile("cp.async.commit_group;" ::: "memory")
#define CP_WAIT2()  asm volatile("cp.async.wait_group 2;" ::: "memory")

__device__ __forceinline__ uint32_t pack_bf16x2(float lo_f, float hi_f) {
    __nv_bfloat162 p(__float2bfloat16(lo_f), __float2bfloat16(hi_f));
    return *reinterpret_cast<uint32_t*>(&p);
}

__device__ __forceinline__ void split4(float4 v, uint2& hv, uint2& lv) {
    float hx = __bfloat162float(__float2bfloat16(v.x));
    float hy = __bfloat162float(__float2bfloat16(v.y));
    float hz = __bfloat162float(__float2bfloat16(v.z));
    float hw = __bfloat162float(__float2bfloat16(v.w));
    hv.x = pack_bf16x2(v.x, v.y);
    hv.y = pack_bf16x2(v.z, v.w);
    lv.x = pack_bf16x2(v.x - hx, v.y - hy);
    lv.y = pack_bf16x2(v.z - hz, v.w - hw);
}

// Stage (one k16): Ahi[0,8K) Alo[8K,16K) Bhi[16K,20K) Blo[20K,24K)
// A = 256 rows x 32B, B = 128 rows x 32B
#define STAGE 24576
#define NSTAGE 4

__device__ __forceinline__ float silu(float x) {
    return x / (1.0f + __expf(-x));
}

// one k16 step: warp tile 64(M) x 64(N), 3 passes; B consumed per 16-row quarter
__device__ __forceinline__ void compute_k16(uint32_t st, float acc[4][8][4],
                                            const uint32_t offA[4],
                                            const uint32_t offB[4]) {
    uint32_t ah[4][4], al[4][4];
    #pragma unroll
    for (int mt = 0; mt < 4; mt++) {
        ldsm4(ah[mt], st + offA[mt]);
        ldsm4(al[mt], st + 8192 + offA[mt]);
    }
    #pragma unroll
    for (int qb = 0; qb < 4; qb++) {
        uint32_t bh[4], bl[4];
        ldsm4(bh, st + 16384 + offB[qb]);
        ldsm4(bl, st + 20480 + offB[qb]);
        #pragma unroll
        for (int mt = 0; mt < 4; mt++) {
            #pragma unroll
            for (int ntl = 0; ntl < 2; ntl++) {
                float* a = acc[mt][qb * 2 + ntl];
                mma_bf16(a, ah[mt], bh[ntl], bh[ntl + 2]);  // hi*hi
                mma_bf16(a, ah[mt], bl[ntl], bl[ntl + 2]);  // hi*lo
                mma_bf16(a, al[mt], bh[ntl], bh[ntl + 2]);  // lo*hi
            }
        }
    }
}

// ---------------- split kernel: fp32 -> bf16 hi/lo ----------------
__global__ void split_kernel(const float4* __restrict__ src,
                             uint2* __restrict__ hi, uint2* __restrict__ lo, long n4)
{
    for (long i = (long)blockIdx.x * blockDim.x + threadIdx.x; i < n4;
         i += (long)gridDim.x * blockDim.x) {
        uint2 h, l;
        split4(src[i], h, l);
        hi[i] = h;
        lo[i] = l;
    }
}

// ---------------- kernel 1: h = silu(x@Wg^T) * (x@Wu^T) ----------------
// CTA: 256 tokens x 64 h-cols. B-tile 128 rows: warp nw gets rows nw*64+j,
// j: qb=j>>4 (col block), p=(j>>3)&1 (0=gate,1=up), ci=j&7.
__global__ __launch_bounds__(256, 1)
void moe_upgate_kernel()
{
    extern __shared__ char smem[];
    const uint32_t smem_b = smem_u32(smem);

    const int tid = threadIdx.x;
    const int lane = tid & 31, warp = tid >> 5;
    const int g = lane >> 2, tg = lane & 3;
    const int nw = warp & 1, mw = warp >> 1;

    const int e = blockIdx.z;
    const int m0 = blockIdx.y * 256;
    const int n0 = blockIdx.x * 64;        // h-col base

    const long arow0 = (long)e * TPE + m0;
    const long brow0 = (long)e * 2 * HIDDEN;

    // cp.async per-thread coords
    const int rowA = tid >> 1, hA = tid & 1;
    const uint32_t dA0 = SW((uint32_t)(rowA * 32 + hA * 16));
    const uint32_t dA1 = SW((uint32_t)((rowA + 128) * 32 + hA * 16));
    const uint32_t dB  = SW((uint32_t)(rowA * 32 + hA * 16));
    const __nv_bfloat16* pA0h = g_x_hi + (arow0 + rowA) * D_MODEL + hA * 8;
    const __nv_bfloat16* pA0l = g_x_lo + (arow0 + rowA) * D_MODEL + hA * 8;
    const __nv_bfloat16* pA1h = pA0h + (long)128 * D_MODEL;
    const __nv_bfloat16* pA1l = pA0l + (long)128 * D_MODEL;
    const int jb = rowA & 63, nwr = rowA >> 6;
    const long grow = brow0 + (((jb >> 3) & 1) ? HIDDEN : 0)
                    + n0 + nwr * 32 + (jb >> 4) * 8 + (jb & 7);
    const __nv_bfloat16* pBh = g_wug_hi + grow * D_MODEL + hA * 8;
    const __nv_bfloat16* pBl = g_wug_lo + grow * D_MODEL + hA * 8;

    // ldmatrix per-lane offsets (loop-invariant)
    uint32_t offA[4], offB[4];
    {
        const int r = lane & 15, h = lane >> 4;
        #pragma unroll
        for (int mt = 0; mt < 4; mt++)
            offA[mt] = SW((uint32_t)((mw * 64 + mt * 16 + r) * 32 + h * 16));
        #pragma unroll
        for (int qb = 0; qb < 4; qb++)
            offB[qb] = SW((uint32_t)((nw * 64 + qb * 16 + r) * 32 + h * 16));
    }

    auto issue = [&]() {
        static_assert(STAGE == 24576, "");
        return;
    };
    (void)issue;

    float acc[4][8][4];
    #pragma unroll
    for (int i = 0; i < 4; i++)
        #pragma unroll
        for (int j = 0; j < 8; j++)
            #pragma unroll
            for (int k = 0; k < 4; k++) acc[i][j][k] = 0.0f;

    const int NCH = D_MODEL / 16;   // 128

    #define ISSUE_STAGE(ST) do { \
        uint32_t _st = (ST); \
        CP_ASYNC16(_st + dA0, pA0h); \
        CP_ASYNC16(_st + 8192 + dA0, pA0l); \
        CP_ASYNC16(_st + dA1, pA1h); \
        CP_ASYNC16(_st + 8192 + dA1, pA1l); \
        CP_ASYNC16(_st + 16384 + dB, pBh); \
        CP_ASYNC16(_st + 20480 + dB, pBl); \
        CP_COMMIT(); \
        pA0h += 16; pA0l += 16; pA1h += 16; pA1l += 16; pBh += 16; pBl += 16; \
    } while (0)

    ISSUE_STAGE(smem_b + 0 * STAGE);
    ISSUE_STAGE(smem_b + 1 * STAGE);
    ISSUE_STAGE(smem_b + 2 * STAGE);

    for (int c = 0; c < NCH; c++) {
        CP_WAIT2();
        __syncthreads();
        if (c + 3 < NCH) { ISSUE_STAGE(smem_b + (uint32_t)((c + 3) & 3) * STAGE); }
        else { CP_COMMIT(); }
        compute_k16(smem_b + (uint32_t)(c & 3) * STAGE, acc, offA, offB);
    }

    // epilogue: acc[mt][2qb]=gate, acc[mt][2qb+1]=up, h-col block nw*32+qb*8
    #pragma unroll
    for (int mt = 0; mt < 4; mt++) {
        long row0 = arow0 + mw * 64 + mt * 16 + g;
        #pragma unroll
        for (int qb = 0; qb < 4; qb++) {
            const float* ga = acc[mt][2 * qb];
            const float* ua = acc[mt][2 * qb + 1];
            int col = n0 + nw * 32 + qb * 8 + tg * 2;
            float vx = silu(ga[0]) * ua[0];
            float vy = silu(ga[1]) * ua[1];
            float vz = silu(ga[2]) * ua[2];
            float vw = silu(ga[3]) * ua[3];
            float hx = __bfloat162float(__float2bfloat16(vx));
            float hy = __bfloat162float(__float2bfloat16(vy));
            float hz = __bfloat162float(__float2bfloat16(vz));
            float hw = __bfloat162float(__float2bfloat16(vw));
            *reinterpret_cast<uint32_t*>(g_h_hi + row0 * HIDDEN + col) = pack_bf16x2(vx, vy);
            *reinterpret_cast<uint32_t*>(g_h_lo + row0 * HIDDEN + col) = pack_bf16x2(vx - hx, vy - hy);
            *reinterpret_cast<uint32_t*>(g_h_hi + (row0 + 8) * HIDDEN + col) = pack_bf16x2(vz, vw);
            *reinterpret_cast<uint32_t*>(g_h_lo + (row0 + 8) * HIDDEN + col) = pack_bf16x2(vz - hz, vw - hw);
        }
    }
    #undef ISSUE_STAGE
}

// ---------------- kernel 2: out = h @ Wd^T ----------------
// CTA: 256 tokens x 128 out-cols; warp 64x64.
__global__ __launch_bounds__(256, 1)
void moe_down_kernel(float* __restrict__ out)
{
    extern __shared__ char smem[];
    const uint32_t smem_b = smem_u32(smem);

    const int tid = threadIdx.x;
    const int lane = tid & 31, warp = tid >> 5;
    const int g = lane >> 2, tg = lane & 3;
    const int nw = warp & 1, mw = warp >> 1;

    const int e = blockIdx.z;
    const int m0 = blockIdx.y * 256;
    const int n0 = blockIdx.x * 128;

    const long arow0 = (long)e * TPE + m0;
    const long bcol0 = (long)e * HIDDEN;

    const int rowA = tid >> 1, hA = tid & 1;
    const uint32_t dA0 = SW((uint32_t)(rowA * 32 + hA * 16));
    const uint32_t dA1 = SW((uint32_t)((rowA + 128) * 32 + hA * 16));
    const uint32_t dB  = SW((uint32_t)(rowA * 32 + hA * 16));
    const __nv_bfloat16* pA0h = g_h_hi + (arow0 + rowA) * HIDDEN + hA * 8;
    const __nv_bfloat16* pA0l = g_h_lo + (arow0 + rowA) * HIDDEN + hA * 8;
    const __nv_bfloat16* pA1h = pA0h + (long)128 * HIDDEN;
    const __nv_bfloat16* pA1l = pA0l + (long)128 * HIDDEN;
    const long growb = (long)(n0 + rowA) * (NUM_EXPERTS * HIDDEN) + bcol0;
    const __nv_bfloat16* pBh = g_wd_hi + growb + hA * 8;
    const __nv_bfloat16* pBl = g_wd_lo + growb + hA * 8;

    uint32_t offA[4], offB[4];
    {
        const int r = lane & 15, h = lane >> 4;
        #pragma unroll
        for (int mt = 0; mt < 4; mt++)
            offA[mt] = SW((uint32_t)((mw * 64 + mt * 16 + r) * 32 + h * 16));
        #pragma unroll
        for (int qb = 0; qb < 4; qb++)
            offB[qb] = SW((uint32_t)((nw * 64 + qb * 16 + r) * 32 + h * 16));
    }

    float acc[4][8][4];
    #pragma unroll
    for (int i = 0; i < 4; i++)
        #pragma unroll
        for (int j = 0; j < 8; j++)
            #pragma unroll
            for (int k = 0; k < 4; k++) acc[i][j][k] = 0.0f;

    const int NCH = HIDDEN / 16;    // 64

    #define ISSUE_STAGE(ST) do { \
        uint32_t _st = (ST); \
        CP_ASYNC16(_st + dA0, pA0h); \
        CP_ASYNC16(_st + 8192 + dA0, pA0l); \
        CP_ASYNC16(_st + dA1, pA1h); \
        CP_ASYNC16(_st + 8192 + dA1, pA1l); \
        CP_ASYNC16(_st + 16384 + dB, pBh); \
        CP_ASYNC16(_st + 20480 + dB, pBl); \
        CP_COMMIT(); \
        pA0h += 16; pA0l += 16; pA1h += 16; pA1l += 16; pBh += 16; pBl += 16; \
    } while (0)

    ISSUE_STAGE(smem_b + 0 * STAGE);
    ISSUE_STAGE(smem_b + 1 * STAGE);
    ISSUE_STAGE(smem_b + 2 * STAGE);

    for (int c = 0; c < NCH; c++) {
        CP_WAIT2();
        __syncthreads();
        if (c + 3 < NCH) { ISSUE_STAGE(smem_b + (uint32_t)((c + 3) & 3) * STAGE); }
        else { CP_COMMIT(); }
        compute_k16(smem_b + (uint32_t)(c & 3) * STAGE, acc, offA, offB);
    }

    #pragma unroll
    for (int mt = 0; mt < 4; mt++) {
        long row0 = arow0 + mw * 64 + mt * 16 + g;
        #pragma unroll
        for (int nt = 0; nt < 8; nt++) {
            int col = n0 + nw * 64 + nt * 8 + tg * 2;
            float2 v0, v1;
            v0.x = acc[mt][nt][0]; v0.y = acc[mt][nt][1];
            v1.x = acc[mt][nt][2]; v1.y = acc[mt][nt][3];
            *reinterpret_cast<float2*>(out + row0 * D_MODEL + col) = v0;
            *reinterpret_cast<float2*>(out + (row0 + 8) * D_MODEL + col) = v1;
        }
    }
    #undef ISSUE_STAGE
}

// ---------------- launch ----------------
extern "C" void kernel_launch(void* const* d_in, const int* in_sizes, int n_in,
                              void* d_out, int out_size)
{
    const float* x        = (const float*)d_in[0];  // [16384, 2048]
    const float* w_upgate = (const float*)d_in[1];  // [E*2H, D]
    const float* w_down   = (const float*)d_in[2];  // [D, E*H]
    float* out = (float*)d_out;

    cudaFuncSetAttribute(moe_upgate_kernel,
                         cudaFuncAttributeMaxDynamicSharedMemorySize, NSTAGE * STAGE);
    cudaFuncSetAttribute(moe_down_kernel,
                         cudaFuncAttributeMaxDynamicSharedMemorySize, NSTAGE * STAGE);

    __nv_bfloat16 *xh, *xl, *ugh, *ugl, *wdh, *wdl;
    cudaGetSymbolAddress((void**)&xh,  g_x_hi);
    cudaGetSymbolAddress((void**)&xl,  g_x_lo);
    cudaGetSymbolAddress((void**)&ugh, g_wug_hi);
    cudaGetSymbolAddress((void**)&ugl, g_wug_lo);
    cudaGetSymbolAddress((void**)&wdh, g_wd_hi);
    cudaGetSymbolAddress((void**)&wdl, g_wd_lo);

    {
        long n4x  = (long)TOTAL_TOKENS * D_MODEL / 4;
        long n4ug = (long)2 * NUM_EXPERTS * HIDDEN * D_MODEL / 4;
        long n4wd = (long)D_MODEL * NUM_EXPERTS * HIDDEN / 4;
        split_kernel<<<2048, 256>>>((const float4*)x, (uint2*)xh, (uint2*)xl, n4x);
        split_kernel<<<2048, 256>>>((const float4*)w_upgate, (uint2*)ugh, (uint2*)ugl, n4ug);
        split_kernel<<<2048, 256>>>((const float4*)w_down, (uint2*)wdh, (uint2*)wdl, n4wd);
    }

    {
        dim3 grid(HIDDEN / 64, TPE / 256, NUM_EXPERTS);   // (16,8,8)
        moe_upgate_kernel<<<grid, 256, NSTAGE * STAGE>>>();
    }
    {
        dim3 grid(D_MODEL / 128, TPE / 256, NUM_EXPERTS); // (16,8,8)
        moe_down_kernel<<<grid, 256, NSTAGE * STAGE>>>(out);
    }
}

// round 8
// speedup vs baseline: 1.7616x; 1.7616x over previous
#include <cuda_runtime.h>
#include <cuda_fp16.h>
#include <cstdint>

#define D_MODEL 2048
#define HIDDEN 1024
#define NUM_EXPERTS 8
#define TPE 2048
#define TOTAL_TOKENS 16384

// fp16 pre-split copies. A-side operands need only the fp16 value (error is
// bounded by its rounding); B-side operands carry hi+lo so B is exact to 2^-22.
__device__ __half g_xh [(size_t)TOTAL_TOKENS * D_MODEL];
__device__ __half g_wugh[(size_t)2 * NUM_EXPERTS * HIDDEN * D_MODEL];
__device__ __half g_wugl[(size_t)2 * NUM_EXPERTS * HIDDEN * D_MODEL];
__device__ __half g_wdh [(size_t)D_MODEL * NUM_EXPERTS * HIDDEN];
__device__ __half g_wdl [(size_t)D_MODEL * NUM_EXPERTS * HIDDEN];
__device__ __half g_hh  [(size_t)TOTAL_TOKENS * HIDDEN];

// ---------------- helpers ----------------
__device__ __forceinline__ uint32_t SW128(uint32_t off) {
    return off ^ ((off >> 3) & 0x70);   // 128B rows, 8-phase swizzle
}

__device__ __forceinline__ uint32_t smem_u32(const void* p) {
    return (uint32_t)__cvta_generic_to_shared(p);
}

__device__ __forceinline__ void mma_f16(float* c, const uint32_t* a,
                                        uint32_t b0, uint32_t b1) {
    asm volatile(
        "mma.sync.aligned.m16n8k16.row.col.f32.f16.f16.f32 "
        "{%0,%1,%2,%3}, {%4,%5,%6,%7}, {%8,%9}, {%0,%1,%2,%3};"
        : "+f"(c[0]), "+f"(c[1]), "+f"(c[2]), "+f"(c[3])
        : "r"(a[0]), "r"(a[1]), "r"(a[2]), "r"(a[3]), "r"(b0), "r"(b1));
}

__device__ __forceinline__ void ldsm4(uint32_t r[4], uint32_t saddr) {
    asm volatile("ldmatrix.sync.aligned.m8n8.x4.shared.b16 {%0,%1,%2,%3}, [%4];"
                 : "=r"(r[0]), "=r"(r[1]), "=r"(r[2]), "=r"(r[3]) : "r"(saddr));
}

#define CP_ASYNC16(dst, src) \
    asm volatile("cp.async.cg.shared.global [%0], [%1], 16;" :: "r"(dst), "l"(src))
#define CP_COMMIT() asm volatile("cp.async.commit_group;" ::: "memory")
#define CP_WAIT2()  asm volatile("cp.async.wait_group 2;" ::: "memory")

__device__ __forceinline__ float silu(float x) {
    return x / (1.0f + __expf(-x));
}

// Stage (one k64): A[0,32K) fp16, Bhi[32K,40K), Blo[40K,48K)
#define STAGE 49152
#define NSTAGE 4
#define SMEM_TOTAL (NSTAGE * STAGE)

// ---------------- split kernels ----------------
__global__ void split_h_kernel(const float4* __restrict__ src,
                               uint2* __restrict__ dst, long n4)
{
    for (long i = (long)blockIdx.x * blockDim.x + threadIdx.x; i < n4;
         i += (long)gridDim.x * blockDim.x) {
        float4 v = src[i];
        __half2 p0(__float2half_rn(v.x), __float2half_rn(v.y));
        __half2 p1(__float2half_rn(v.z), __float2half_rn(v.w));
        uint2 o;
        o.x = *reinterpret_cast<uint32_t*>(&p0);
        o.y = *reinterpret_cast<uint32_t*>(&p1);
        dst[i] = o;
    }
}

__global__ void split_hl_kernel(const float4* __restrict__ src,
                                uint2* __restrict__ hi, uint2* __restrict__ lo, long n4)
{
    for (long i = (long)blockIdx.x * blockDim.x + threadIdx.x; i < n4;
         i += (long)gridDim.x * blockDim.x) {
        float4 v = src[i];
        __half hx = __float2half_rn(v.x), hy = __float2half_rn(v.y);
        __half hz = __float2half_rn(v.z), hw = __float2half_rn(v.w);
        __half2 h0(hx, hy), h1(hz, hw);
        __half2 l0(__float2half_rn(v.x - __half2float(hx)),
                   __float2half_rn(v.y - __half2float(hy)));
        __half2 l1(__float2half_rn(v.z - __half2float(hz)),
                   __float2half_rn(v.w - __half2float(hw)));
        uint2 oh, ol;
        oh.x = *reinterpret_cast<uint32_t*>(&h0);
        oh.y = *reinterpret_cast<uint32_t*>(&h1);
        ol.x = *reinterpret_cast<uint32_t*>(&l0);
        ol.y = *reinterpret_cast<uint32_t*>(&l1);
        hi[i] = oh;
        lo[i] = ol;
    }
}

// ---------------- compute: one k64 stage, warp tile 64(M) x 32(N), 2 passes ----
__device__ __forceinline__ void compute_k64(uint32_t st, float acc[4][4][4],
                                            int lane, int mw, int nw)
{
    const int r = lane & 15;
    const uint32_t h16 = (uint32_t)(lane >> 4) << 4;

    #pragma unroll
    for (int ks = 0; ks < 4; ks++) {
        const uint32_t kc = (uint32_t)ks * 32 + h16;
        uint32_t a[4][4], bh[2][4], bl[2][4];

        #pragma unroll
        for (int mt = 0; mt < 4; mt++) {
            uint32_t rowa = (uint32_t)(mw * 64 + mt * 16 + r);
            uint32_t off = rowa * 128 + (kc ^ ((rowa & 7) << 4));
            ldsm4(a[mt], st + off);
        }
        #pragma unroll
        for (int pr = 0; pr < 2; pr++) {
            uint32_t rowb = (uint32_t)(nw * 32 + pr * 16 + r);
            uint32_t off = rowb * 128 + (kc ^ ((rowb & 7) << 4));
            ldsm4(bh[pr], st + 32768 + off);
            ldsm4(bl[pr], st + 40960 + off);
        }

        // pass 1: A x Bhi
        #pragma unroll
        for (int mt = 0; mt < 4; mt++)
            #pragma unroll
            for (int nt = 0; nt < 4; nt++)
                mma_f16(acc[mt][nt], a[mt], bh[nt >> 1][nt & 1], bh[nt >> 1][(nt & 1) + 2]);
        // pass 2: A x Blo
        #pragma unroll
        for (int mt = 0; mt < 4; mt++)
            #pragma unroll
            for (int nt = 0; nt < 4; nt++)
                mma_f16(acc[mt][nt], a[mt], bl[nt >> 1][nt & 1], bl[nt >> 1][(nt & 1) + 2]);
    }
}

// ---------------- kernel 1: h = silu(x@Wg^T) * (x@Wu^T) ----------------
// CTA: 256 tokens x 64 B-rows (= 32 h-cols; gate/up interleaved per 16 rows).
// 8 warps = 4 mw x 2 nw; warp tile 64 x 32.
__global__ __launch_bounds__(256, 1)
void moe_upgate_kernel()
{
    extern __shared__ char smem[];
    const uint32_t smem_b = smem_u32(smem);

    const int tid = threadIdx.x;
    const int lane = tid & 31, warp = tid >> 5;
    const int g = lane >> 2, tg = lane & 3;
    const int nw = warp & 1, mw = warp >> 1;

    const int e = blockIdx.z;
    const int m0 = blockIdx.y * 256;
    const int n0 = blockIdx.x * 32;        // h-col base

    const long arow0 = (long)e * TPE + m0;
    const long brow0 = (long)e * 2 * HIDDEN;

    // cp.async per-thread setup
    const int trow = tid >> 3, tc16 = tid & 7;
    uint32_t dA[8], dB[2];
    #pragma unroll
    for (int it = 0; it < 8; it++)
        dA[it] = SW128((uint32_t)((trow + it * 32) * 128 + tc16 * 16));
    #pragma unroll
    for (int it = 0; it < 2; it++)
        dB[it] = SW128((uint32_t)((trow + it * 32) * 128 + tc16 * 16));

    const __half* pA = g_xh + (arow0 + trow) * D_MODEL + tc16 * 8;
    const __half* pBh[2];
    const __half* pBl[2];
    #pragma unroll
    for (int it = 0; it < 2; it++) {
        int row = trow + it * 32;
        int nwr = row >> 5, jj = row & 31, p = jj >> 4, cc = jj & 15;
        long grow = brow0 + (p ? HIDDEN : 0) + n0 + nwr * 16 + cc;
        pBh[it] = g_wugh + grow * D_MODEL + tc16 * 8;
        pBl[it] = g_wugl + grow * D_MODEL + tc16 * 8;
    }

    #define ISSUE_UG(SIDX, K0) do { \
        uint32_t _s = smem_b + (uint32_t)(SIDX) * STAGE; \
        _Pragma("unroll") \
        for (int _it = 0; _it < 8; _it++) \
            CP_ASYNC16(_s + dA[_it], pA + (long)_it * 32 * D_MODEL + (K0)); \
        _Pragma("unroll") \
        for (int _it = 0; _it < 2; _it++) { \
            CP_ASYNC16(_s + 32768 + dB[_it], pBh[_it] + (K0)); \
            CP_ASYNC16(_s + 40960 + dB[_it], pBl[_it] + (K0)); \
        } \
        CP_COMMIT(); \
    } while (0)

    float acc[4][4][4];
    #pragma unroll
    for (int i = 0; i < 4; i++)
        #pragma unroll
        for (int j = 0; j < 4; j++)
            #pragma unroll
            for (int k = 0; k < 4; k++) acc[i][j][k] = 0.0f;

    const int NCH = D_MODEL / 64;   // 32

    ISSUE_UG(0, 0);
    ISSUE_UG(1, 64);
    ISSUE_UG(2, 128);

    for (int c = 0; c < NCH; c++) {
        CP_WAIT2();
        __syncthreads();
        if (c + 3 < NCH) { ISSUE_UG((c + 3) & 3, (long)(c + 3) * 64); }
        else { CP_COMMIT(); }
        compute_k64(smem_b + (uint32_t)(c & 3) * STAGE, acc, lane, mw, nw);
    }
    #undef ISSUE_UG

    // epilogue: acc[mt][ntl] = gate (pr=0), acc[mt][2+ntl] = up (pr=1)
    #pragma unroll
    for (int mt = 0; mt < 4; mt++) {
        long row0 = arow0 + mw * 64 + mt * 16 + g;
        #pragma unroll
        for (int ntl = 0; ntl < 2; ntl++) {
            const float* ga = acc[mt][ntl];
            const float* ua = acc[mt][2 + ntl];
            int col = n0 + nw * 16 + ntl * 8 + tg * 2;
            __half2 v0(__float2half_rn(silu(ga[0]) * ua[0]),
                       __float2half_rn(silu(ga[1]) * ua[1]));
            __half2 v1(__float2half_rn(silu(ga[2]) * ua[2]),
                       __float2half_rn(silu(ga[3]) * ua[3]));
            *reinterpret_cast<__half2*>(g_hh + row0 * HIDDEN + col) = v0;
            *reinterpret_cast<__half2*>(g_hh + (row0 + 8) * HIDDEN + col) = v1;
        }
    }
}

// ---------------- kernel 2: out = h @ Wd^T ----------------
// CTA: 256 tokens x 64 out-cols; warp tile 64 x 32.
__global__ __launch_bounds__(256, 1)
void moe_down_kernel(float* __restrict__ out)
{
    extern __shared__ char smem[];
    const uint32_t smem_b = smem_u32(smem);

    const int tid = threadIdx.x;
    const int lane = tid & 31, warp = tid >> 5;
    const int g = lane >> 2, tg = lane & 3;
    const int nw = warp & 1, mw = warp >> 1;

    const int e = blockIdx.z;
    const int m0 = blockIdx.y * 256;
    const int n0 = blockIdx.x * 64;

    const long arow0 = (long)e * TPE + m0;

    const int trow = tid >> 3, tc16 = tid & 7;
    uint32_t dA[8], dB[2];
    #pragma unroll
    for (int it = 0; it < 8; it++)
        dA[it] = SW128((uint32_t)((trow + it * 32) * 128 + tc16 * 16));
    #pragma unroll
    for (int it = 0; it < 2; it++)
        dB[it] = SW128((uint32_t)((trow + it * 32) * 128 + tc16 * 16));

    const __half* pA = g_hh + (arow0 + trow) * HIDDEN + tc16 * 8;
    const __half* pBh[2];
    const __half* pBl[2];
    #pragma unroll
    for (int it = 0; it < 2; it++) {
        long brow = (long)(n0 + trow + it * 32) * (NUM_EXPERTS * HIDDEN)
                  + (long)e * HIDDEN;
        pBh[it] = g_wdh + brow + tc16 * 8;
        pBl[it] = g_wdl + brow + tc16 * 8;
    }

    #define ISSUE_DN(SIDX, K0) do { \
        uint32_t _s = smem_b + (uint32_t)(SIDX) * STAGE; \
        _Pragma("unroll") \
        for (int _it = 0; _it < 8; _it++) \
            CP_ASYNC16(_s + dA[_it], pA + (long)_it * 32 * HIDDEN + (K0)); \
        _Pragma("unroll") \
        for (int _it = 0; _it < 2; _it++) { \
            CP_ASYNC16(_s + 32768 + dB[_it], pBh[_it] + (K0)); \
            CP_ASYNC16(_s + 40960 + dB[_it], pBl[_it] + (K0)); \
        } \
        CP_COMMIT(); \
    } while (0)

    float acc[4][4][4];
    #pragma unroll
    for (int i = 0; i < 4; i++)
        #pragma unroll
        for (int j = 0; j < 4; j++)
            #pragma unroll
            for (int k = 0; k < 4; k++) acc[i][j][k] = 0.0f;

    const int NCH = HIDDEN / 64;    // 16

    ISSUE_DN(0, 0);
    ISSUE_DN(1, 64);
    ISSUE_DN(2, 128);

    for (int c = 0; c < NCH; c++) {
        CP_WAIT2();
        __syncthreads();
        if (c + 3 < NCH) { ISSUE_DN((c + 3) & 3, (long)(c + 3) * 64); }
        else { CP_COMMIT(); }
        compute_k64(smem_b + (uint32_t)(c & 3) * STAGE, acc, lane, mw, nw);
    }
    #undef ISSUE_DN

    #pragma unroll
    for (int mt = 0; mt < 4; mt++) {
        long row0 = arow0 + mw * 64 + mt * 16 + g;
        #pragma unroll
        for (int nt = 0; nt < 4; nt++) {
            int col = n0 + nw * 32 + (nt >> 1) * 16 + (nt & 1) * 8 + tg * 2;
            float2 v0, v1;
            v0.x = acc[mt][nt][0]; v0.y = acc[mt][nt][1];
            v1.x = acc[mt][nt][2]; v1.y = acc[mt][nt][3];
            *reinterpret_cast<float2*>(out + row0 * D_MODEL + col) = v0;
            *reinterpret_cast<float2*>(out + (row0 + 8) * D_MODEL + col) = v1;
        }
    }
}

// ---------------- launch ----------------
extern "C" void kernel_launch(void* const* d_in, const int* in_sizes, int n_in,
                              void* d_out, int out_size)
{
    const float* x        = (const float*)d_in[0];  // [16384, 2048]
    const float* w_upgate = (const float*)d_in[1];  // [E*2H, D]
    const float* w_down   = (const float*)d_in[2];  // [D, E*H]
    float* out = (float*)d_out;

    cudaFuncSetAttribute(moe_upgate_kernel,
                         cudaFuncAttributeMaxDynamicSharedMemorySize, SMEM_TOTAL);
    cudaFuncSetAttribute(moe_down_kernel,
                         cudaFuncAttributeMaxDynamicSharedMemorySize, SMEM_TOTAL);

    __half *xh, *ugh, *ugl, *wdh, *wdl;
    cudaGetSymbolAddress((void**)&xh,  g_xh);
    cudaGetSymbolAddress((void**)&ugh, g_wugh);
    cudaGetSymbolAddress((void**)&ugl, g_wugl);
    cudaGetSymbolAddress((void**)&wdh, g_wdh);
    cudaGetSymbolAddress((void**)&wdl, g_wdl);

    {
        long n4x  = (long)TOTAL_TOKENS * D_MODEL / 4;
        long n4ug = (long)2 * NUM_EXPERTS * HIDDEN * D_MODEL / 4;
        long n4wd = (long)D_MODEL * NUM_EXPERTS * HIDDEN / 4;
        split_h_kernel<<<2048, 256>>>((const float4*)x, (uint2*)xh, n4x);
        split_hl_kernel<<<2048, 256>>>((const float4*)w_upgate, (uint2*)ugh, (uint2*)ugl, n4ug);
        split_hl_kernel<<<2048, 256>>>((const float4*)w_down, (uint2*)wdh, (uint2*)wdl, n4wd);
    }

    {
        dim3 grid(HIDDEN / 32, TPE / 256, NUM_EXPERTS);   // (32,8,8)
        moe_upgate_kernel<<<grid, 256, SMEM_TOTAL>>>();
    }
    {
        dim3 grid(D_MODEL / 64, TPE / 256, NUM_EXPERTS);  // (32,8,8)
        moe_down_kernel<<<grid, 256, SMEM_TOTAL>>>(out);
    }
}

// round 9
// speedup vs baseline: 1.8524x; 1.0516x over previous
#include <cuda_runtime.h>
#include <cuda_fp16.h>
#include <cstdint>

#define D_MODEL 2048
#define HIDDEN 1024
#define NUM_EXPERTS 8
#define TPE 2048
#define TOTAL_TOKENS 16384

// fp16 pre-split copies. A-side operands use the fp16 value only (error
// bounded by its rounding); B-side operands carry hi+lo so B is exact to 2^-22.
__device__ __half g_xh [(size_t)TOTAL_TOKENS * D_MODEL];
__device__ __half g_wugh[(size_t)2 * NUM_EXPERTS * HIDDEN * D_MODEL];
__device__ __half g_wugl[(size_t)2 * NUM_EXPERTS * HIDDEN * D_MODEL];
__device__ __half g_wdh [(size_t)D_MODEL * NUM_EXPERTS * HIDDEN];
__device__ __half g_wdl [(size_t)D_MODEL * NUM_EXPERTS * HIDDEN];
__device__ __half g_hh  [(size_t)TOTAL_TOKENS * HIDDEN];

// ---------------- helpers ----------------
// 64B rows; XOR bits[5:4] with bits[8:7] -> conflict-free ldmatrix & cp.async STS
__device__ __forceinline__ uint32_t SW64(uint32_t off) {
    return off ^ ((off >> 3) & 0x30);
}

__device__ __forceinline__ uint32_t smem_u32(const void* p) {
    return (uint32_t)__cvta_generic_to_shared(p);
}

__device__ __forceinline__ void mma_f16(float* c, const uint32_t* a,
                                        uint32_t b0, uint32_t b1) {
    asm volatile(
        "mma.sync.aligned.m16n8k16.row.col.f32.f16.f16.f32 "
        "{%0,%1,%2,%3}, {%4,%5,%6,%7}, {%8,%9}, {%0,%1,%2,%3};"
        : "+f"(c[0]), "+f"(c[1]), "+f"(c[2]), "+f"(c[3])
        : "r"(a[0]), "r"(a[1]), "r"(a[2]), "r"(a[3]), "r"(b0), "r"(b1));
}

__device__ __forceinline__ void ldsm4(uint32_t r[4], uint32_t saddr) {
    asm volatile("ldmatrix.sync.aligned.m8n8.x4.shared.b16 {%0,%1,%2,%3}, [%4];"
                 : "=r"(r[0]), "=r"(r[1]), "=r"(r[2]), "=r"(r[3]) : "r"(saddr));
}

#define CP_ASYNC16(dst, src) \
    asm volatile("cp.async.cg.shared.global [%0], [%1], 16;" :: "r"(dst), "l"(src))
#define CP_COMMIT() asm volatile("cp.async.commit_group;" ::: "memory")
#define CP_WAIT2()  asm volatile("cp.async.wait_group 2;" ::: "memory")

__device__ __forceinline__ float silu(float x) {
    return x / (1.0f + __expf(-x));
}

// Stage (one k32): A[0,16K) fp16 (256 rows x 64B), Bhi[16K,20K), Blo[20K,24K)
#define STAGE 24576
#define NSTAGE 4
#define SMEM_TOTAL (NSTAGE * STAGE)   // 96 KB -> 2 CTAs/SM

// ---------------- split kernels ----------------
__global__ void split_h_kernel(const float4* __restrict__ src,
                               uint2* __restrict__ dst, long n4)
{
    for (long i = (long)blockIdx.x * blockDim.x + threadIdx.x; i < n4;
         i += (long)gridDim.x * blockDim.x) {
        float4 v = src[i];
        __half2 p0(__float2half_rn(v.x), __float2half_rn(v.y));
        __half2 p1(__float2half_rn(v.z), __float2half_rn(v.w));
        uint2 o;
        o.x = *reinterpret_cast<uint32_t*>(&p0);
        o.y = *reinterpret_cast<uint32_t*>(&p1);
        dst[i] = o;
    }
}

__global__ void split_hl_kernel(const float4* __restrict__ src,
                                uint2* __restrict__ hi, uint2* __restrict__ lo, long n4)
{
    for (long i = (long)blockIdx.x * blockDim.x + threadIdx.x; i < n4;
         i += (long)gridDim.x * blockDim.x) {
        float4 v = src[i];
        __half hx = __float2half_rn(v.x), hy = __float2half_rn(v.y);
        __half hz = __float2half_rn(v.z), hw = __float2half_rn(v.w);
        __half2 h0(hx, hy), h1(hz, hw);
        __half2 l0(__float2half_rn(v.x - __half2float(hx)),
                   __float2half_rn(v.y - __half2float(hy)));
        __half2 l1(__float2half_rn(v.z - __half2float(hz)),
                   __float2half_rn(v.w - __half2float(hw)));
        uint2 oh, ol;
        oh.x = *reinterpret_cast<uint32_t*>(&h0);
        oh.y = *reinterpret_cast<uint32_t*>(&h1);
        ol.x = *reinterpret_cast<uint32_t*>(&l0);
        ol.y = *reinterpret_cast<uint32_t*>(&l1);
        hi[i] = oh;
        lo[i] = ol;
    }
}

// ---------------- compute: one k32 stage, warp tile 64(M) x 32(N), 2 passes ----
__device__ __forceinline__ void compute_k32(uint32_t st, float acc[4][4][4],
                                            int lane, int mw, int nw)
{
    const int r = lane & 15;
    const uint32_t h16 = (uint32_t)(lane >> 4) << 4;

    #pragma unroll
    for (int ks = 0; ks < 2; ks++) {
        const uint32_t kc = (uint32_t)ks * 32 + h16;
        uint32_t a[4][4], bh[2][4], bl[2][4];

        #pragma unroll
        for (int mt = 0; mt < 4; mt++) {
            uint32_t R = (uint32_t)(mw * 64 + mt * 16 + r) * 64;
            ldsm4(a[mt], st + R + (kc ^ ((R >> 3) & 0x30)));
        }
        #pragma unroll
        for (int pr = 0; pr < 2; pr++) {
            uint32_t R = (uint32_t)(nw * 32 + pr * 16 + r) * 64;
            uint32_t off = R + (kc ^ ((R >> 3) & 0x30));
            ldsm4(bh[pr], st + 16384 + off);
            ldsm4(bl[pr], st + 20480 + off);
        }

        #pragma unroll
        for (int mt = 0; mt < 4; mt++)
            #pragma unroll
            for (int nt = 0; nt < 4; nt++)
                mma_f16(acc[mt][nt], a[mt], bh[nt >> 1][nt & 1], bh[nt >> 1][(nt & 1) + 2]);
        #pragma unroll
        for (int mt = 0; mt < 4; mt++)
            #pragma unroll
            for (int nt = 0; nt < 4; nt++)
                mma_f16(acc[mt][nt], a[mt], bl[nt >> 1][nt & 1], bl[nt >> 1][(nt & 1) + 2]);
    }
}

// ---------------- kernel 1: h = silu(x@Wg^T) * (x@Wu^T) ----------------
// CTA: 256 tokens x 64 B-rows (32 h-cols; gate/up interleaved per 16 rows).
// 8 warps = 4 mw x 2 nw; warp tile 64 x 32.
__global__ __launch_bounds__(256, 2)
void moe_upgate_kernel()
{
    extern __shared__ char smem[];
    const uint32_t smem_b = smem_u32(smem);

    const int tid = threadIdx.x;
    const int lane = tid & 31, warp = tid >> 5;
    const int g = lane >> 2, tg = lane & 3;
    const int nw = warp & 1, mw = warp >> 1;

    const int e = blockIdx.z;
    const int m0 = blockIdx.y * 256;
    const int n0 = blockIdx.x * 32;        // h-col base

    const long arow0 = (long)e * TPE + m0;
    const long brow0 = (long)e * 2 * HIDDEN;

    // cp.async per-thread coords: A rows 0..255 (4 iters), B rows 0..63 (1 iter)
    const int trow = tid >> 2, tc16 = tid & 3;
    uint32_t dA[4];
    #pragma unroll
    for (int it = 0; it < 4; it++)
        dA[it] = SW64((uint32_t)((trow + it * 64) * 64 + tc16 * 16));
    const uint32_t dB = SW64((uint32_t)(trow * 64 + tc16 * 16));

    const __half* pA = g_xh + (arow0 + trow) * D_MODEL + tc16 * 8;
    const int nwr = trow >> 5, jj = trow & 31, pgu = jj >> 4, cc = jj & 15;
    const long grow = brow0 + (pgu ? HIDDEN : 0) + n0 + nwr * 16 + cc;
    const __half* pBh = g_wugh + grow * D_MODEL + tc16 * 8;
    const __half* pBl = g_wugl + grow * D_MODEL + tc16 * 8;

    #define ISSUE_UG(SIDX, K0) do { \
        uint32_t _s = smem_b + (uint32_t)(SIDX) * STAGE; \
        _Pragma("unroll") \
        for (int _it = 0; _it < 4; _it++) \
            CP_ASYNC16(_s + dA[_it], pA + (long)_it * 64 * D_MODEL + (K0)); \
        CP_ASYNC16(_s + 16384 + dB, pBh + (K0)); \
        CP_ASYNC16(_s + 20480 + dB, pBl + (K0)); \
        CP_COMMIT(); \
    } while (0)

    float acc[4][4][4];
    #pragma unroll
    for (int i = 0; i < 4; i++)
        #pragma unroll
        for (int j = 0; j < 4; j++)
            #pragma unroll
            for (int k = 0; k < 4; k++) acc[i][j][k] = 0.0f;

    const int NCH = D_MODEL / 32;   // 64

    ISSUE_UG(0, 0);
    ISSUE_UG(1, 32);
    ISSUE_UG(2, 64);

    for (int c = 0; c < NCH; c++) {
        CP_WAIT2();
        __syncthreads();
        if (c + 3 < NCH) { ISSUE_UG((c + 3) & 3, (long)(c + 3) * 32); }
        else { CP_COMMIT(); }
        compute_k32(smem_b + (uint32_t)(c & 3) * STAGE, acc, lane, mw, nw);
    }
    #undef ISSUE_UG

    // epilogue: acc[mt][ntl] = gate (pr=0), acc[mt][2+ntl] = up (pr=1)
    #pragma unroll
    for (int mt = 0; mt < 4; mt++) {
        long row0 = arow0 + mw * 64 + mt * 16 + g;
        #pragma unroll
        for (int ntl = 0; ntl < 2; ntl++) {
            const float* ga = acc[mt][ntl];
            const float* ua = acc[mt][2 + ntl];
            int col = n0 + nw * 16 + ntl * 8 + tg * 2;
            __half2 v0(__float2half_rn(silu(ga[0]) * ua[0]),
                       __float2half_rn(silu(ga[1]) * ua[1]));
            __half2 v1(__float2half_rn(silu(ga[2]) * ua[2]),
                       __float2half_rn(silu(ga[3]) * ua[3]));
            *reinterpret_cast<__half2*>(g_hh + row0 * HIDDEN + col) = v0;
            *reinterpret_cast<__half2*>(g_hh + (row0 + 8) * HIDDEN + col) = v1;
        }
    }
}

// ---------------- kernel 2: out = h @ Wd^T ----------------
// CTA: 256 tokens x 64 out-cols; warp tile 64 x 32.
__global__ __launch_bounds__(256, 2)
void moe_down_kernel(float* __restrict__ out)
{
    extern __shared__ char smem[];
    const uint32_t smem_b = smem_u32(smem);

    const int tid = threadIdx.x;
    const int lane = tid & 31, warp = tid >> 5;
    const int g = lane >> 2, tg = lane & 3;
    const int nw = warp & 1, mw = warp >> 1;

    const int e = blockIdx.z;
    const int m0 = blockIdx.y * 256;
    const int n0 = blockIdx.x * 64;

    const long arow0 = (long)e * TPE + m0;

    const int trow = tid >> 2, tc16 = tid & 3;
    uint32_t dA[4];
    #pragma unroll
    for (int it = 0; it < 4; it++)
        dA[it] = SW64((uint32_t)((trow + it * 64) * 64 + tc16 * 16));
    const uint32_t dB = SW64((uint32_t)(trow * 64 + tc16 * 16));

    const __half* pA = g_hh + (arow0 + trow) * HIDDEN + tc16 * 8;
    const long browb = (long)(n0 + trow) * (NUM_EXPERTS * HIDDEN) + (long)e * HIDDEN;
    const __half* pBh = g_wdh + browb + tc16 * 8;
    const __half* pBl = g_wdl + browb + tc16 * 8;

    #define ISSUE_DN(SIDX, K0) do { \
        uint32_t _s = smem_b + (uint32_t)(SIDX) * STAGE; \
        _Pragma("unroll") \
        for (int _it = 0; _it < 4; _it++) \
            CP_ASYNC16(_s + dA[_it], pA + (long)_it * 64 * HIDDEN + (K0)); \
        CP_ASYNC16(_s + 16384 + dB, pBh + (K0)); \
        CP_ASYNC16(_s + 20480 + dB, pBl + (K0)); \
        CP_COMMIT(); \
    } while (0)

    float acc[4][4][4];
    #pragma unroll
    for (int i = 0; i < 4; i++)
        #pragma unroll
        for (int j = 0; j < 4; j++)
            #pragma unroll
            for (int k = 0; k < 4; k++) acc[i][j][k] = 0.0f;

    const int NCH = HIDDEN / 32;    // 32

    ISSUE_DN(0, 0);
    ISSUE_DN(1, 32);
    ISSUE_DN(2, 64);

    for (int c = 0; c < NCH; c++) {
        CP_WAIT2();
        __syncthreads();
        if (c + 3 < NCH) { ISSUE_DN((c + 3) & 3, (long)(c + 3) * 32); }
        else { CP_COMMIT(); }
        compute_k32(smem_b + (uint32_t)(c & 3) * STAGE, acc, lane, mw, nw);
    }
    #undef ISSUE_DN

    #pragma unroll
    for (int mt = 0; mt < 4; mt++) {
        long row0 = arow0 + mw * 64 + mt * 16 + g;
        #pragma unroll
        for (int nt = 0; nt < 4; nt++) {
            int col = n0 + nw * 32 + (nt >> 1) * 16 + (nt & 1) * 8 + tg * 2;
            float2 v0, v1;
            v0.x = acc[mt][nt][0]; v0.y = acc[mt][nt][1];
            v1.x = acc[mt][nt][2]; v1.y = acc[mt][nt][3];
            *reinterpret_cast<float2*>(out + row0 * D_MODEL + col) = v0;
            *reinterpret_cast<float2*>(out + (row0 + 8) * D_MODEL + col) = v1;
        }
    }
}

// ---------------- launch ----------------
extern "C" void kernel_launch(void* const* d_in, const int* in_sizes, int n_in,
                              void* d_out, int out_size)
{
    const float* x        = (const float*)d_in[0];  // [16384, 2048]
    const float* w_upgate = (const float*)d_in[1];  // [E*2H, D]
    const float* w_down   = (const float*)d_in[2];  // [D, E*H]
    float* out = (float*)d_out;

    cudaFuncSetAttribute(moe_upgate_kernel,
                         cudaFuncAttributeMaxDynamicSharedMemorySize, SMEM_TOTAL);
    cudaFuncSetAttribute(moe_down_kernel,
                         cudaFuncAttributeMaxDynamicSharedMemorySize, SMEM_TOTAL);

    __half *xh, *ugh, *ugl, *wdh, *wdl;
    cudaGetSymbolAddress((void**)&xh,  g_xh);
    cudaGetSymbolAddress((void**)&ugh, g_wugh);
    cudaGetSymbolAddress((void**)&ugl, g_wugl);
    cudaGetSymbolAddress((void**)&wdh, g_wdh);
    cudaGetSymbolAddress((void**)&wdl, g_wdl);

    {
        long n4x  = (long)TOTAL_TOKENS * D_MODEL / 4;
        long n4ug = (long)2 * NUM_EXPERTS * HIDDEN * D_MODEL / 4;
        long n4wd = (long)D_MODEL * NUM_EXPERTS * HIDDEN / 4;
        split_h_kernel<<<2048, 256>>>((const float4*)x, (uint2*)xh, n4x);
        split_hl_kernel<<<2048, 256>>>((const float4*)w_upgate, (uint2*)ugh, (uint2*)ugl, n4ug);
        split_hl_kernel<<<2048, 256>>>((const float4*)w_down, (uint2*)wdh, (uint2*)wdl, n4wd);
    }

    {
        dim3 grid(HIDDEN / 32, TPE / 256, NUM_EXPERTS);   // (32,8,8)
        moe_upgate_kernel<<<grid, 256, SMEM_TOTAL>>>();
    }
    {
        dim3 grid(D_MODEL / 64, TPE / 256, NUM_EXPERTS);  // (32,8,8)
        moe_down_kernel<<<grid, 256, SMEM_TOTAL>>>(out);
    }
}

// round 10
// speedup vs baseline: 1.8607x; 1.0045x over previous
#include <cuda_runtime.h>
#include <cuda_fp16.h>
#include <cstdint>

#define D_MODEL 2048
#define HIDDEN 1024
#define NUM_EXPERTS 8
#define TPE 2048
#define TOTAL_TOKENS 16384

// fp16 pre-split copies. A-side operands use the fp16 value only (error
// bounded by its rounding); B-side operands carry hi+lo so B is exact to 2^-22.
__device__ __half g_xh [(size_t)TOTAL_TOKENS * D_MODEL];
__device__ __half g_wugh[(size_t)2 * NUM_EXPERTS * HIDDEN * D_MODEL];
__device__ __half g_wugl[(size_t)2 * NUM_EXPERTS * HIDDEN * D_MODEL];
__device__ __half g_wdh [(size_t)D_MODEL * NUM_EXPERTS * HIDDEN];
__device__ __half g_wdl [(size_t)D_MODEL * NUM_EXPERTS * HIDDEN];
__device__ __half g_hh  [(size_t)TOTAL_TOKENS * HIDDEN];

// ---------------- helpers ----------------
// 64B rows; XOR bits[5:4] with bits[8:7] -> conflict-free ldmatrix & cp.async STS
__device__ __forceinline__ uint32_t SW64(uint32_t off) {
    return off ^ ((off >> 3) & 0x30);
}

__device__ __forceinline__ uint32_t smem_u32(const void* p) {
    return (uint32_t)__cvta_generic_to_shared(p);
}

__device__ __forceinline__ void mma_f16(float* c, const uint32_t* a,
                                        uint32_t b0, uint32_t b1) {
    asm volatile(
        "mma.sync.aligned.m16n8k16.row.col.f32.f16.f16.f32 "
        "{%0,%1,%2,%3}, {%4,%5,%6,%7}, {%8,%9}, {%0,%1,%2,%3};"
        : "+f"(c[0]), "+f"(c[1]), "+f"(c[2]), "+f"(c[3])
        : "r"(a[0]), "r"(a[1]), "r"(a[2]), "r"(a[3]), "r"(b0), "r"(b1));
}

__device__ __forceinline__ void ldsm4(uint32_t r[4], uint32_t saddr) {
    asm volatile("ldmatrix.sync.aligned.m8n8.x4.shared.b16 {%0,%1,%2,%3}, [%4];"
                 : "=r"(r[0]), "=r"(r[1]), "=r"(r[2]), "=r"(r[3]) : "r"(saddr));
}

#define CP_ASYNC16(dst, src) \
    asm volatile("cp.async.cg.shared.global [%0], [%1], 16;" :: "r"(dst), "l"(src))
#define CP_COMMIT() asm volatile("cp.async.commit_group;" ::: "memory")
#define CP_WAIT0()  asm volatile("cp.async.wait_group 0;" ::: "memory")

__device__ __forceinline__ float silu(float x) {
    return x / (1.0f + __expf(-x));
}

// Stage (one k32): A[0,16K) fp16 (256 rows x 64B), Bhi[16K,20K), Blo[20K,24K)
#define STAGE 24576
#define NSTAGE 4
#define SMEM_TOTAL (NSTAGE * STAGE)   // 96 KB -> 2 CTAs/SM

// ---------------- split kernels ----------------
__global__ void split_h_kernel(const float4* __restrict__ src,
                               uint2* __restrict__ dst, long n4)
{
    for (long i = (long)blockIdx.x * blockDim.x + threadIdx.x; i < n4;
         i += (long)gridDim.x * blockDim.x) {
        float4 v = src[i];
        __half2 p0(__float2half_rn(v.x), __float2half_rn(v.y));
        __half2 p1(__float2half_rn(v.z), __float2half_rn(v.w));
        uint2 o;
        o.x = *reinterpret_cast<uint32_t*>(&p0);
        o.y = *reinterpret_cast<uint32_t*>(&p1);
        dst[i] = o;
    }
}

__global__ void split_hl_kernel(const float4* __restrict__ src,
                                uint2* __restrict__ hi, uint2* __restrict__ lo, long n4)
{
    for (long i = (long)blockIdx.x * blockDim.x + threadIdx.x; i < n4;
         i += (long)gridDim.x * blockDim.x) {
        float4 v = src[i];
        __half hx = __float2half_rn(v.x), hy = __float2half_rn(v.y);
        __half hz = __float2half_rn(v.z), hw = __float2half_rn(v.w);
        __half2 h0(hx, hy), h1(hz, hw);
        __half2 l0(__float2half_rn(v.x - __half2float(hx)),
                   __float2half_rn(v.y - __half2float(hy)));
        __half2 l1(__float2half_rn(v.z - __half2float(hz)),
                   __float2half_rn(v.w - __half2float(hw)));
        uint2 oh, ol;
        oh.x = *reinterpret_cast<uint32_t*>(&h0);
        oh.y = *reinterpret_cast<uint32_t*>(&h1);
        ol.x = *reinterpret_cast<uint32_t*>(&l0);
        ol.y = *reinterpret_cast<uint32_t*>(&l1);
        hi[i] = oh;
        lo[i] = ol;
    }
}

// ---------------- compute: one k32 stage, warp tile 64(M) x 32(N), 2 passes ----
__device__ __forceinline__ void compute_k32(uint32_t st, float acc[4][4][4],
                                            int lane, int mw, int nw)
{
    const int r = lane & 15;
    const uint32_t h16 = (uint32_t)(lane >> 4) << 4;

    #pragma unroll
    for (int ks = 0; ks < 2; ks++) {
        const uint32_t kc = (uint32_t)ks * 32 + h16;
        uint32_t a[4][4], bh[2][4], bl[2][4];

        #pragma unroll
        for (int mt = 0; mt < 4; mt++) {
            uint32_t R = (uint32_t)(mw * 64 + mt * 16 + r) * 64;
            ldsm4(a[mt], st + R + (kc ^ ((R >> 3) & 0x30)));
        }
        #pragma unroll
        for (int pr = 0; pr < 2; pr++) {
            uint32_t R = (uint32_t)(nw * 32 + pr * 16 + r) * 64;
            uint32_t off = R + (kc ^ ((R >> 3) & 0x30));
            ldsm4(bh[pr], st + 16384 + off);
            ldsm4(bl[pr], st + 20480 + off);
        }

        #pragma unroll
        for (int mt = 0; mt < 4; mt++)
            #pragma unroll
            for (int nt = 0; nt < 4; nt++)
                mma_f16(acc[mt][nt], a[mt], bh[nt >> 1][nt & 1], bh[nt >> 1][(nt & 1) + 2]);
        #pragma unroll
        for (int mt = 0; mt < 4; mt++)
            #pragma unroll
            for (int nt = 0; nt < 4; nt++)
                mma_f16(acc[mt][nt], a[mt], bl[nt >> 1][nt & 1], bl[nt >> 1][(nt & 1) + 2]);
    }
}

// ---------------- kernel 1: h = silu(x@Wg^T) * (x@Wu^T) ----------------
// CTA: 256 tokens x 64 B-rows (32 h-cols; gate/up interleaved per 16 rows).
// 8 warps = 4 mw x 2 nw; warp tile 64 x 32. Two k32 chunks per barrier.
__global__ __launch_bounds__(256, 2)
void moe_upgate_kernel()
{
    extern __shared__ char smem[];
    const uint32_t smem_b = smem_u32(smem);

    const int tid = threadIdx.x;
    const int lane = tid & 31, warp = tid >> 5;
    const int g = lane >> 2, tg = lane & 3;
    const int nw = warp & 1, mw = warp >> 1;

    const int e = blockIdx.z;
    const int m0 = blockIdx.y * 256;
    const int n0 = blockIdx.x * 32;        // h-col base

    const long arow0 = (long)e * TPE + m0;
    const long brow0 = (long)e * 2 * HIDDEN;

    // cp.async per-thread coords: A rows 0..255 (4 iters), B rows 0..63 (1 iter)
    const int trow = tid >> 2, tc16 = tid & 3;
    uint32_t dA[4];
    #pragma unroll
    for (int it = 0; it < 4; it++)
        dA[it] = SW64((uint32_t)((trow + it * 64) * 64 + tc16 * 16));
    const uint32_t dB = SW64((uint32_t)(trow * 64 + tc16 * 16));

    const __half* pA = g_xh + (arow0 + trow) * D_MODEL + tc16 * 8;
    const int nwr = trow >> 5, jj = trow & 31, pgu = jj >> 4, cc = jj & 15;
    const long grow = brow0 + (pgu ? HIDDEN : 0) + n0 + nwr * 16 + cc;
    const __half* pBh = g_wugh + grow * D_MODEL + tc16 * 8;
    const __half* pBl = g_wugl + grow * D_MODEL + tc16 * 8;

    #define ISSUE_UG(SIDX, K0) do { \
        uint32_t _s = smem_b + (uint32_t)(SIDX) * STAGE; \
        _Pragma("unroll") \
        for (int _it = 0; _it < 4; _it++) \
            CP_ASYNC16(_s + dA[_it], pA + (long)_it * 64 * D_MODEL + (K0)); \
        CP_ASYNC16(_s + 16384 + dB, pBh + (K0)); \
        CP_ASYNC16(_s + 20480 + dB, pBl + (K0)); \
    } while (0)

    float acc[4][4][4];
    #pragma unroll
    for (int i = 0; i < 4; i++)
        #pragma unroll
        for (int j = 0; j < 4; j++)
            #pragma unroll
            for (int k = 0; k < 4; k++) acc[i][j][k] = 0.0f;

    const int NPAIR = (D_MODEL / 32) / 2;   // 32 pairs of k32 chunks

    // prologue: pair 0 -> stages 0,1 (single commit group)
    ISSUE_UG(0, 0);
    ISSUE_UG(1, 32);
    CP_COMMIT();

    for (int p = 0; p < NPAIR; p++) {
        CP_WAIT0();
        __syncthreads();
        if (p + 1 < NPAIR) {
            // pair p+1 -> stages freed by the barrier (ring distance 2)
            ISSUE_UG((2 * p + 2) & 3, (long)(2 * p + 2) * 32);
            ISSUE_UG((2 * p + 3) & 3, (long)(2 * p + 3) * 32);
            CP_COMMIT();
        }
        compute_k32(smem_b + (uint32_t)((2 * p) & 3) * STAGE, acc, lane, mw, nw);
        compute_k32(smem_b + (uint32_t)((2 * p + 1) & 3) * STAGE, acc, lane, mw, nw);
    }
    #undef ISSUE_UG

    // epilogue: acc[mt][ntl] = gate (pr=0), acc[mt][2+ntl] = up (pr=1)
    #pragma unroll
    for (int mt = 0; mt < 4; mt++) {
        long row0 = arow0 + mw * 64 + mt * 16 + g;
        #pragma unroll
        for (int ntl = 0; ntl < 2; ntl++) {
            const float* ga = acc[mt][ntl];
            const float* ua = acc[mt][2 + ntl];
            int col = n0 + nw * 16 + ntl * 8 + tg * 2;
            __half2 v0(__float2half_rn(silu(ga[0]) * ua[0]),
                       __float2half_rn(silu(ga[1]) * ua[1]));
            __half2 v1(__float2half_rn(silu(ga[2]) * ua[2]),
                       __float2half_rn(silu(ga[3]) * ua[3]));
            *reinterpret_cast<__half2*>(g_hh + row0 * HIDDEN + col) = v0;
            *reinterpret_cast<__half2*>(g_hh + (row0 + 8) * HIDDEN + col) = v1;
        }
    }
}

// ---------------- kernel 2: out = h @ Wd^T ----------------
// CTA: 256 tokens x 64 out-cols; warp tile 64 x 32. Two chunks per barrier.
__global__ __launch_bounds__(256, 2)
void moe_down_kernel(float* __restrict__ out)
{
    extern __shared__ char smem[];
    const uint32_t smem_b = smem_u32(smem);

    const int tid = threadIdx.x;
    const int lane = tid & 31, warp = tid >> 5;
    const int g = lane >> 2, tg = lane & 3;
    const int nw = warp & 1, mw = warp >> 1;

    const int e = blockIdx.z;
    const int m0 = blockIdx.y * 256;
    const int n0 = blockIdx.x * 64;

    const long arow0 = (long)e * TPE + m0;

    const int trow = tid >> 2, tc16 = tid & 3;
    uint32_t dA[4];
    #pragma unroll
    for (int it = 0; it < 4; it++)
        dA[it] = SW64((uint32_t)((trow + it * 64) * 64 + tc16 * 16));
    const uint32_t dB = SW64((uint32_t)(trow * 64 + tc16 * 16));

    const __half* pA = g_hh + (arow0 + trow) * HIDDEN + tc16 * 8;
    const long browb = (long)(n0 + trow) * (NUM_EXPERTS * HIDDEN) + (long)e * HIDDEN;
    const __half* pBh = g_wdh + browb + tc16 * 8;
    const __half* pBl = g_wdl + browb + tc16 * 8;

    #define ISSUE_DN(SIDX, K0) do { \
        uint32_t _s = smem_b + (uint32_t)(SIDX) * STAGE; \
        _Pragma("unroll") \
        for (int _it = 0; _it < 4; _it++) \
            CP_ASYNC16(_s + dA[_it], pA + (long)_it * 64 * HIDDEN + (K0)); \
        CP_ASYNC16(_s + 16384 + dB, pBh + (K0)); \
        CP_ASYNC16(_s + 20480 + dB, pBl + (K0)); \
    } while (0)

    float acc[4][4][4];
    #pragma unroll
    for (int i = 0; i < 4; i++)
        #pragma unroll
        for (int j = 0; j < 4; j++)
            #pragma unroll
            for (int k = 0; k < 4; k++) acc[i][j][k] = 0.0f;

    const int NPAIR = (HIDDEN / 32) / 2;    // 16 pairs

    ISSUE_DN(0, 0);
    ISSUE_DN(1, 32);
    CP_COMMIT();

    for (int p = 0; p < NPAIR; p++) {
        CP_WAIT0();
        __syncthreads();
        if (p + 1 < NPAIR) {
            ISSUE_DN((2 * p + 2) & 3, (long)(2 * p + 2) * 32);
            ISSUE_DN((2 * p + 3) & 3, (long)(2 * p + 3) * 32);
            CP_COMMIT();
        }
        compute_k32(smem_b + (uint32_t)((2 * p) & 3) * STAGE, acc, lane, mw, nw);
        compute_k32(smem_b + (uint32_t)((2 * p + 1) & 3) * STAGE, acc, lane, mw, nw);
    }
    #undef ISSUE_DN

    #pragma unroll
    for (int mt = 0; mt < 4; mt++) {
        long row0 = arow0 + mw * 64 + mt * 16 + g;
        #pragma unroll
        for (int nt = 0; nt < 4; nt++) {
            int col = n0 + nw * 32 + (nt >> 1) * 16 + (nt & 1) * 8 + tg * 2;
            float2 v0, v1;
            v0.x = acc[mt][nt][0]; v0.y = acc[mt][nt][1];
            v1.x = acc[mt][nt][2]; v1.y = acc[mt][nt][3];
            *reinterpret_cast<float2*>(out + row0 * D_MODEL + col) = v0;
            *reinterpret_cast<float2*>(out + (row0 + 8) * D_MODEL + col) = v1;
        }
    }
}

// ---------------- launch ----------------
extern "C" void kernel_launch(void* const* d_in, const int* in_sizes, int n_in,
                              void* d_out, int out_size)
{
    const float* x        = (const float*)d_in[0];  // [16384, 2048]
    const float* w_upgate = (const float*)d_in[1];  // [E*2H, D]
    const float* w_down   = (const float*)d_in[2];  // [D, E*H]
    float* out = (float*)d_out;

    cudaFuncSetAttribute(moe_upgate_kernel,
                         cudaFuncAttributeMaxDynamicSharedMemorySize, SMEM_TOTAL);
    cudaFuncSetAttribute(moe_down_kernel,
                         cudaFuncAttributeMaxDynamicSharedMemorySize, SMEM_TOTAL);

    __half *xh, *ugh, *ugl, *wdh, *wdl;
    cudaGetSymbolAddress((void**)&xh,  g_xh);
    cudaGetSymbolAddress((void**)&ugh, g_wugh);
    cudaGetSymbolAddress((void**)&ugl, g_wugl);
    cudaGetSymbolAddress((void**)&wdh, g_wdh);
    cudaGetSymbolAddress((void**)&wdl, g_wdl);

    {
        long n4x  = (long)TOTAL_TOKENS * D_MODEL / 4;
        long n4ug = (long)2 * NUM_EXPERTS * HIDDEN * D_MODEL / 4;
        long n4wd = (long)D_MODEL * NUM_EXPERTS * HIDDEN / 4;
        split_h_kernel<<<2048, 256>>>((const float4*)x, (uint2*)xh, n4x);
        split_hl_kernel<<<2048, 256>>>((const float4*)w_upgate, (uint2*)ugh, (uint2*)ugl, n4ug);
        split_hl_kernel<<<2048, 256>>>((const float4*)w_down, (uint2*)wdh, (uint2*)wdl, n4wd);
    }

    {
        dim3 grid(HIDDEN / 32, TPE / 256, NUM_EXPERTS);   // (32,8,8)
        moe_upgate_kernel<<<grid, 256, SMEM_TOTAL>>>();
    }
    {
        dim3 grid(D_MODEL / 64, TPE / 256, NUM_EXPERTS);  // (32,8,8)
        moe_down_kernel<<<grid, 256, SMEM_TOTAL>>>(out);
    }
}

// round 11
// speedup vs baseline: 2.1277x; 1.1435x over previous
#include <cuda_runtime.h>
#include <cuda_fp16.h>
#include <cstdint>

#define D_MODEL 2048
#define HIDDEN 1024
#define NUM_EXPERTS 8
#define TPE 2048
#define TOTAL_TOKENS 16384

// fp16 pre-split copies. GEMM1: A=x fp16 (1 copy), B=wug hi+lo (2-pass, exact).
// GEMM2: A=h fp16, B=wd fp16 single-pass (error budget allows it).
__device__ __half g_xh [(size_t)TOTAL_TOKENS * D_MODEL];
__device__ __half g_wugh[(size_t)2 * NUM_EXPERTS * HIDDEN * D_MODEL];
__device__ __half g_wugl[(size_t)2 * NUM_EXPERTS * HIDDEN * D_MODEL];
__device__ __half g_wdh [(size_t)D_MODEL * NUM_EXPERTS * HIDDEN];
__device__ __half g_hh  [(size_t)TOTAL_TOKENS * HIDDEN];

// ---------------- helpers ----------------
// 64B rows; XOR bits[5:4] with bits[8:7] -> conflict-free ldmatrix & cp.async STS
__device__ __forceinline__ uint32_t SW64(uint32_t off) {
    return off ^ ((off >> 3) & 0x30);
}

__device__ __forceinline__ uint32_t smem_u32(const void* p) {
    return (uint32_t)__cvta_generic_to_shared(p);
}

__device__ __forceinline__ void mma_f16(float* c, const uint32_t* a,
                                        uint32_t b0, uint32_t b1) {
    asm volatile(
        "mma.sync.aligned.m16n8k16.row.col.f32.f16.f16.f32 "
        "{%0,%1,%2,%3}, {%4,%5,%6,%7}, {%8,%9}, {%0,%1,%2,%3};"
        : "+f"(c[0]), "+f"(c[1]), "+f"(c[2]), "+f"(c[3])
        : "r"(a[0]), "r"(a[1]), "r"(a[2]), "r"(a[3]), "r"(b0), "r"(b1));
}

__device__ __forceinline__ void ldsm4(uint32_t r[4], uint32_t saddr) {
    asm volatile("ldmatrix.sync.aligned.m8n8.x4.shared.b16 {%0,%1,%2,%3}, [%4];"
                 : "=r"(r[0]), "=r"(r[1]), "=r"(r[2]), "=r"(r[3]) : "r"(saddr));
}

#define CP_ASYNC16(dst, src) \
    asm volatile("cp.async.cg.shared.global [%0], [%1], 16;" :: "r"(dst), "l"(src))
#define CP_COMMIT() asm volatile("cp.async.commit_group;" ::: "memory")
#define CP_WAIT0()  asm volatile("cp.async.wait_group 0;" ::: "memory")

__device__ __forceinline__ float silu(float x) {
    return x / (1.0f + __expf(-x));
}

// GEMM1 stage (k32): A[0,16K) fp16 (256x64B), Bhi[16K,20K), Blo[20K,24K)
#define STAGE_UG 24576
#define SMEM_UG (4 * STAGE_UG)     // 96 KB -> 2 CTAs/SM
// GEMM2 stage (k32): A[0,16K), B[16K,20K)
#define STAGE_DN 20480
#define SMEM_DN (4 * STAGE_DN)     // 80 KB -> 2 CTAs/SM

// ---------------- split kernels ----------------
__global__ void split_h_kernel(const float4* __restrict__ src,
                               uint2* __restrict__ dst, long n4)
{
    for (long i = (long)blockIdx.x * blockDim.x + threadIdx.x; i < n4;
         i += (long)gridDim.x * blockDim.x) {
        float4 v = src[i];
        __half2 p0(__float2half_rn(v.x), __float2half_rn(v.y));
        __half2 p1(__float2half_rn(v.z), __float2half_rn(v.w));
        uint2 o;
        o.x = *reinterpret_cast<uint32_t*>(&p0);
        o.y = *reinterpret_cast<uint32_t*>(&p1);
        dst[i] = o;
    }
}

__global__ void split_hl_kernel(const float4* __restrict__ src,
                                uint2* __restrict__ hi, uint2* __restrict__ lo, long n4)
{
    for (long i = (long)blockIdx.x * blockDim.x + threadIdx.x; i < n4;
         i += (long)gridDim.x * blockDim.x) {
        float4 v = src[i];
        __half hx = __float2half_rn(v.x), hy = __float2half_rn(v.y);
        __half hz = __float2half_rn(v.z), hw = __float2half_rn(v.w);
        __half2 h0(hx, hy), h1(hz, hw);
        __half2 l0(__float2half_rn(v.x - __half2float(hx)),
                   __float2half_rn(v.y - __half2float(hy)));
        __half2 l1(__float2half_rn(v.z - __half2float(hz)),
                   __float2half_rn(v.w - __half2float(hw)));
        uint2 oh, ol;
        oh.x = *reinterpret_cast<uint32_t*>(&h0);
        oh.y = *reinterpret_cast<uint32_t*>(&h1);
        ol.x = *reinterpret_cast<uint32_t*>(&l0);
        ol.y = *reinterpret_cast<uint32_t*>(&l1);
        hi[i] = oh;
        lo[i] = ol;
    }
}

// ---------------- GEMM1 compute: k32, warp 64x32, 2 passes (Bhi, Blo) ----------
__device__ __forceinline__ void compute_k32_2p(uint32_t st, float acc[4][4][4],
                                               int lane, int mw, int nw)
{
    const int r = lane & 15;
    const uint32_t h16 = (uint32_t)(lane >> 4) << 4;

    #pragma unroll
    for (int ks = 0; ks < 2; ks++) {
        const uint32_t kc = (uint32_t)ks * 32 + h16;
        uint32_t a[4][4], bh[2][4], bl[2][4];

        #pragma unroll
        for (int mt = 0; mt < 4; mt++) {
            uint32_t R = (uint32_t)(mw * 64 + mt * 16 + r) * 64;
            ldsm4(a[mt], st + R + (kc ^ ((R >> 3) & 0x30)));
        }
        #pragma unroll
        for (int pr = 0; pr < 2; pr++) {
            uint32_t R = (uint32_t)(nw * 32 + pr * 16 + r) * 64;
            uint32_t off = R + (kc ^ ((R >> 3) & 0x30));
            ldsm4(bh[pr], st + 16384 + off);
            ldsm4(bl[pr], st + 20480 + off);
        }

        #pragma unroll
        for (int mt = 0; mt < 4; mt++)
            #pragma unroll
            for (int nt = 0; nt < 4; nt++)
                mma_f16(acc[mt][nt], a[mt], bh[nt >> 1][nt & 1], bh[nt >> 1][(nt & 1) + 2]);
        #pragma unroll
        for (int mt = 0; mt < 4; mt++)
            #pragma unroll
            for (int nt = 0; nt < 4; nt++)
                mma_f16(acc[mt][nt], a[mt], bl[nt >> 1][nt & 1], bl[nt >> 1][(nt & 1) + 2]);
    }
}

// ---------------- GEMM2 compute: k32, warp 64x32, single pass ----------------
__device__ __forceinline__ void compute_k32_1p(uint32_t st, float acc[4][4][4],
                                               int lane, int mw, int nw)
{
    const int r = lane & 15;
    const uint32_t h16 = (uint32_t)(lane >> 4) << 4;

    #pragma unroll
    for (int ks = 0; ks < 2; ks++) {
        const uint32_t kc = (uint32_t)ks * 32 + h16;
        uint32_t a[4][4], bh[2][4];

        #pragma unroll
        for (int mt = 0; mt < 4; mt++) {
            uint32_t R = (uint32_t)(mw * 64 + mt * 16 + r) * 64;
            ldsm4(a[mt], st + R + (kc ^ ((R >> 3) & 0x30)));
        }
        #pragma unroll
        for (int pr = 0; pr < 2; pr++) {
            uint32_t R = (uint32_t)(nw * 32 + pr * 16 + r) * 64;
            ldsm4(bh[pr], st + 16384 + (R + (kc ^ ((R >> 3) & 0x30))));
        }

        #pragma unroll
        for (int mt = 0; mt < 4; mt++)
            #pragma unroll
            for (int nt = 0; nt < 4; nt++)
                mma_f16(acc[mt][nt], a[mt], bh[nt >> 1][nt & 1], bh[nt >> 1][(nt & 1) + 2]);
    }
}

// ---------------- kernel 1: h = silu(x@Wg^T) * (x@Wu^T) ----------------
// CTA: 256 tokens x 64 B-rows (32 h-cols; gate/up interleaved per 16 rows).
// 8 warps = 4 mw x 2 nw; warp tile 64 x 32. Two k32 chunks per barrier.
__global__ __launch_bounds__(256, 2)
void moe_upgate_kernel()
{
    extern __shared__ char smem[];
    const uint32_t smem_b = smem_u32(smem);

    const int tid = threadIdx.x;
    const int lane = tid & 31, warp = tid >> 5;
    const int g = lane >> 2, tg = lane & 3;
    const int nw = warp & 1, mw = warp >> 1;

    const int e = blockIdx.z;
    const int m0 = blockIdx.y * 256;
    const int n0 = blockIdx.x * 32;        // h-col base

    const long arow0 = (long)e * TPE + m0;
    const long brow0 = (long)e * 2 * HIDDEN;

    const int trow = tid >> 2, tc16 = tid & 3;
    uint32_t dA[4];
    #pragma unroll
    for (int it = 0; it < 4; it++)
        dA[it] = SW64((uint32_t)((trow + it * 64) * 64 + tc16 * 16));
    const uint32_t dB = SW64((uint32_t)(trow * 64 + tc16 * 16));

    const __half* pA = g_xh + (arow0 + trow) * D_MODEL + tc16 * 8;
    const int nwr = trow >> 5, jj = trow & 31, pgu = jj >> 4, cc = jj & 15;
    const long grow = brow0 + (pgu ? HIDDEN : 0) + n0 + nwr * 16 + cc;
    const __half* pBh = g_wugh + grow * D_MODEL + tc16 * 8;
    const __half* pBl = g_wugl + grow * D_MODEL + tc16 * 8;

    #define ISSUE_UG(SIDX, K0) do { \
        uint32_t _s = smem_b + (uint32_t)(SIDX) * STAGE_UG; \
        _Pragma("unroll") \
        for (int _it = 0; _it < 4; _it++) \
            CP_ASYNC16(_s + dA[_it], pA + (long)_it * 64 * D_MODEL + (K0)); \
        CP_ASYNC16(_s + 16384 + dB, pBh + (K0)); \
        CP_ASYNC16(_s + 20480 + dB, pBl + (K0)); \
    } while (0)

    float acc[4][4][4];
    #pragma unroll
    for (int i = 0; i < 4; i++)
        #pragma unroll
        for (int j = 0; j < 4; j++)
            #pragma unroll
            for (int k = 0; k < 4; k++) acc[i][j][k] = 0.0f;

    const int NPAIR = (D_MODEL / 32) / 2;   // 32 pairs

    ISSUE_UG(0, 0);
    ISSUE_UG(1, 32);
    CP_COMMIT();

    for (int p = 0; p < NPAIR; p++) {
        CP_WAIT0();
        __syncthreads();
        if (p + 1 < NPAIR) {
            ISSUE_UG((2 * p + 2) & 3, (long)(2 * p + 2) * 32);
            ISSUE_UG((2 * p + 3) & 3, (long)(2 * p + 3) * 32);
            CP_COMMIT();
        }
        compute_k32_2p(smem_b + (uint32_t)((2 * p) & 3) * STAGE_UG, acc, lane, mw, nw);
        compute_k32_2p(smem_b + (uint32_t)((2 * p + 1) & 3) * STAGE_UG, acc, lane, mw, nw);
    }
    #undef ISSUE_UG

    // epilogue: acc[mt][ntl] = gate (pr=0), acc[mt][2+ntl] = up (pr=1)
    #pragma unroll
    for (int mt = 0; mt < 4; mt++) {
        long row0 = arow0 + mw * 64 + mt * 16 + g;
        #pragma unroll
        for (int ntl = 0; ntl < 2; ntl++) {
            const float* ga = acc[mt][ntl];
            const float* ua = acc[mt][2 + ntl];
            int col = n0 + nw * 16 + ntl * 8 + tg * 2;
            __half2 v0(__float2half_rn(silu(ga[0]) * ua[0]),
                       __float2half_rn(silu(ga[1]) * ua[1]));
            __half2 v1(__float2half_rn(silu(ga[2]) * ua[2]),
                       __float2half_rn(silu(ga[3]) * ua[3]));
            *reinterpret_cast<__half2*>(g_hh + row0 * HIDDEN + col) = v0;
            *reinterpret_cast<__half2*>(g_hh + (row0 + 8) * HIDDEN + col) = v1;
        }
    }
}

// ---------------- kernel 2: out = h @ Wd^T (single-pass B) ----------------
// CTA: 256 tokens x 64 out-cols; warp tile 64 x 32. Two chunks per barrier.
__global__ __launch_bounds__(256, 2)
void moe_down_kernel(float* __restrict__ out)
{
    extern __shared__ char smem[];
    const uint32_t smem_b = smem_u32(smem);

    const int tid = threadIdx.x;
    const int lane = tid & 31, warp = tid >> 5;
    const int g = lane >> 2, tg = lane & 3;
    const int nw = warp & 1, mw = warp >> 1;

    const int e = blockIdx.z;
    const int m0 = blockIdx.y * 256;
    const int n0 = blockIdx.x * 64;

    const long arow0 = (long)e * TPE + m0;

    const int trow = tid >> 2, tc16 = tid & 3;
    uint32_t dA[4];
    #pragma unroll
    for (int it = 0; it < 4; it++)
        dA[it] = SW64((uint32_t)((trow + it * 64) * 64 + tc16 * 16));
    const uint32_t dB = SW64((uint32_t)(trow * 64 + tc16 * 16));

    const __half* pA = g_hh + (arow0 + trow) * HIDDEN + tc16 * 8;
    const long browb = (long)(n0 + trow) * (NUM_EXPERTS * HIDDEN) + (long)e * HIDDEN;
    const __half* pBh = g_wdh + browb + tc16 * 8;

    #define ISSUE_DN(SIDX, K0) do { \
        uint32_t _s = smem_b + (uint32_t)(SIDX) * STAGE_DN; \
        _Pragma("unroll") \
        for (int _it = 0; _it < 4; _it++) \
            CP_ASYNC16(_s + dA[_it], pA + (long)_it * 64 * HIDDEN + (K0)); \
        CP_ASYNC16(_s + 16384 + dB, pBh + (K0)); \
    } while (0)

    float acc[4][4][4];
    #pragma unroll
    for (int i = 0; i < 4; i++)
        #pragma unroll
        for (int j = 0; j < 4; j++)
            #pragma unroll
            for (int k = 0; k < 4; k++) acc[i][j][k] = 0.0f;

    const int NPAIR = (HIDDEN / 32) / 2;    // 16 pairs

    ISSUE_DN(0, 0);
    ISSUE_DN(1, 32);
    CP_COMMIT();

    for (int p = 0; p < NPAIR; p++) {
        CP_WAIT0();
        __syncthreads();
        if (p + 1 < NPAIR) {
            ISSUE_DN((2 * p + 2) & 3, (long)(2 * p + 2) * 32);
            ISSUE_DN((2 * p + 3) & 3, (long)(2 * p + 3) * 32);
            CP_COMMIT();
        }
        compute_k32_1p(smem_b + (uint32_t)((2 * p) & 3) * STAGE_DN, acc, lane, mw, nw);
        compute_k32_1p(smem_b + (uint32_t)((2 * p + 1) & 3) * STAGE_DN, acc, lane, mw, nw);
    }
    #undef ISSUE_DN

    #pragma unroll
    for (int mt = 0; mt < 4; mt++) {
        long row0 = arow0 + mw * 64 + mt * 16 + g;
        #pragma unroll
        for (int nt = 0; nt < 4; nt++) {
            int col = n0 + nw * 32 + (nt >> 1) * 16 + (nt & 1) * 8 + tg * 2;
            float2 v0, v1;
            v0.x = acc[mt][nt][0]; v0.y = acc[mt][nt][1];
            v1.x = acc[mt][nt][2]; v1.y = acc[mt][nt][3];
            *reinterpret_cast<float2*>(out + row0 * D_MODEL + col) = v0;
            *reinterpret_cast<float2*>(out + (row0 + 8) * D_MODEL + col) = v1;
        }
    }
}

// ---------------- launch ----------------
extern "C" void kernel_launch(void* const* d_in, const int* in_sizes, int n_in,
                              void* d_out, int out_size)
{
    const float* x        = (const float*)d_in[0];  // [16384, 2048]
    const float* w_upgate = (const float*)d_in[1];  // [E*2H, D]
    const float* w_down   = (const float*)d_in[2];  // [D, E*H]
    float* out = (float*)d_out;

    cudaFuncSetAttribute(moe_upgate_kernel,
                         cudaFuncAttributeMaxDynamicSharedMemorySize, SMEM_UG);
    cudaFuncSetAttribute(moe_down_kernel,
                         cudaFuncAttributeMaxDynamicSharedMemorySize, SMEM_DN);

    __half *xh, *ugh, *ugl, *wdh;
    cudaGetSymbolAddress((void**)&xh,  g_xh);
    cudaGetSymbolAddress((void**)&ugh, g_wugh);
    cudaGetSymbolAddress((void**)&ugl, g_wugl);
    cudaGetSymbolAddress((void**)&wdh, g_wdh);

    {
        long n4x  = (long)TOTAL_TOKENS * D_MODEL / 4;
        long n4ug = (long)2 * NUM_EXPERTS * HIDDEN * D_MODEL / 4;
        long n4wd = (long)D_MODEL * NUM_EXPERTS * HIDDEN / 4;
        split_h_kernel<<<2048, 256>>>((const float4*)x, (uint2*)xh, n4x);
        split_hl_kernel<<<2048, 256>>>((const float4*)w_upgate, (uint2*)ugh, (uint2*)ugl, n4ug);
        split_h_kernel<<<2048, 256>>>((const float4*)w_down, (uint2*)wdh, n4wd);
    }

    {
        dim3 grid(HIDDEN / 32, TPE / 256, NUM_EXPERTS);   // (32,8,8)
        moe_upgate_kernel<<<grid, 256, SMEM_UG>>>();
    }
    {
        dim3 grid(D_MODEL / 64, TPE / 256, NUM_EXPERTS);  // (32,8,8)
        moe_down_kernel<<<grid, 256, SMEM_DN>>>(out);
    }
}

// round 12
// speedup vs baseline: 3.0074x; 1.4135x over previous
#include <cuda_runtime.h>
#include <cuda_fp16.h>
#include <cstdint>

#define D_MODEL 2048
#define HIDDEN 1024
#define NUM_EXPERTS 8
#define TPE 2048
#define TOTAL_TOKENS 16384

// fp16 copies (single-pass HMMA everywhere; error = 5 calibrated rounding
// sources ~2.57e-4 RMS each -> ~5.8e-4 total, under the 1e-3 gate).
__device__ __half g_xh [(size_t)TOTAL_TOKENS * D_MODEL];
__device__ __half g_wugh[(size_t)2 * NUM_EXPERTS * HIDDEN * D_MODEL];
__device__ __half g_wdh [(size_t)D_MODEL * NUM_EXPERTS * HIDDEN];
__device__ __half g_hh  [(size_t)TOTAL_TOKENS * HIDDEN];

// ---------------- helpers ----------------
// 64B rows; XOR bits[5:4] with bits[8:7] -> conflict-free ldmatrix & cp.async STS
__device__ __forceinline__ uint32_t SW64(uint32_t off) {
    return off ^ ((off >> 3) & 0x30);
}

__device__ __forceinline__ uint32_t smem_u32(const void* p) {
    return (uint32_t)__cvta_generic_to_shared(p);
}

__device__ __forceinline__ void mma_f16(float* c, const uint32_t* a,
                                        uint32_t b0, uint32_t b1) {
    asm volatile(
        "mma.sync.aligned.m16n8k16.row.col.f32.f16.f16.f32 "
        "{%0,%1,%2,%3}, {%4,%5,%6,%7}, {%8,%9}, {%0,%1,%2,%3};"
        : "+f"(c[0]), "+f"(c[1]), "+f"(c[2]), "+f"(c[3])
        : "r"(a[0]), "r"(a[1]), "r"(a[2]), "r"(a[3]), "r"(b0), "r"(b1));
}

__device__ __forceinline__ void ldsm4(uint32_t r[4], uint32_t saddr) {
    asm volatile("ldmatrix.sync.aligned.m8n8.x4.shared.b16 {%0,%1,%2,%3}, [%4];"
                 : "=r"(r[0]), "=r"(r[1]), "=r"(r[2]), "=r"(r[3]) : "r"(saddr));
}

#define CP_ASYNC16(dst, src) \
    asm volatile("cp.async.cg.shared.global [%0], [%1], 16;" :: "r"(dst), "l"(src))
#define CP_COMMIT() asm volatile("cp.async.commit_group;" ::: "memory")
#define CP_WAIT0()  asm volatile("cp.async.wait_group 0;" ::: "memory")

__device__ __forceinline__ float silu(float x) {
    return x / (1.0f + __expf(-x));
}

// Stage (one k32): A[0,16K) fp16 (256 rows x 64B), B[16K,20K) (64 rows x 64B)
#define STAGE 20480
#define SMEM_TOTAL (4 * STAGE)     // 80 KB -> 2 CTAs/SM

// ---------------- split kernel: fp32 -> fp16 ----------------
__global__ void split_h_kernel(const float4* __restrict__ src,
                               uint2* __restrict__ dst, long n4)
{
    for (long i = (long)blockIdx.x * blockDim.x + threadIdx.x; i < n4;
         i += (long)gridDim.x * blockDim.x) {
        float4 v = src[i];
        __half2 p0(__float2half_rn(v.x), __float2half_rn(v.y));
        __half2 p1(__float2half_rn(v.z), __float2half_rn(v.w));
        uint2 o;
        o.x = *reinterpret_cast<uint32_t*>(&p0);
        o.y = *reinterpret_cast<uint32_t*>(&p1);
        dst[i] = o;
    }
}

// ---------------- compute: one k32 stage, warp tile 64x32, single pass -------
__device__ __forceinline__ void compute_k32(uint32_t st, float acc[4][4][4],
                                            int lane, int mw, int nw)
{
    const int r = lane & 15;
    const uint32_t h16 = (uint32_t)(lane >> 4) << 4;

    #pragma unroll
    for (int ks = 0; ks < 2; ks++) {
        const uint32_t kc = (uint32_t)ks * 32 + h16;
        uint32_t a[4][4], bh[2][4];

        #pragma unroll
        for (int mt = 0; mt < 4; mt++) {
            uint32_t R = (uint32_t)(mw * 64 + mt * 16 + r) * 64;
            ldsm4(a[mt], st + R + (kc ^ ((R >> 3) & 0x30)));
        }
        #pragma unroll
        for (int pr = 0; pr < 2; pr++) {
            uint32_t R = (uint32_t)(nw * 32 + pr * 16 + r) * 64;
            ldsm4(bh[pr], st + 16384 + (R + (kc ^ ((R >> 3) & 0x30))));
        }

        #pragma unroll
        for (int mt = 0; mt < 4; mt++)
            #pragma unroll
            for (int nt = 0; nt < 4; nt++)
                mma_f16(acc[mt][nt], a[mt], bh[nt >> 1][nt & 1], bh[nt >> 1][(nt & 1) + 2]);
    }
}

// ---------------- kernel 1: h = silu(x@Wg^T) * (x@Wu^T) ----------------
// CTA: 256 tokens x 64 B-rows (32 h-cols; gate/up interleaved per 16 rows).
// 8 warps = 4 mw x 2 nw; warp tile 64 x 32. Two k32 chunks per barrier.
__global__ __launch_bounds__(256, 2)
void moe_upgate_kernel()
{
    extern __shared__ char smem[];
    const uint32_t smem_b = smem_u32(smem);

    const int tid = threadIdx.x;
    const int lane = tid & 31, warp = tid >> 5;
    const int g = lane >> 2, tg = lane & 3;
    const int nw = warp & 1, mw = warp >> 1;

    const int e = blockIdx.z;
    const int m0 = blockIdx.y * 256;
    const int n0 = blockIdx.x * 32;        // h-col base

    const long arow0 = (long)e * TPE + m0;
    const long brow0 = (long)e * 2 * HIDDEN;

    const int trow = tid >> 2, tc16 = tid & 3;
    uint32_t dA[4];
    #pragma unroll
    for (int it = 0; it < 4; it++)
        dA[it] = SW64((uint32_t)((trow + it * 64) * 64 + tc16 * 16));
    const uint32_t dB = SW64((uint32_t)(trow * 64 + tc16 * 16));

    const __half* pA = g_xh + (arow0 + trow) * D_MODEL + tc16 * 8;
    const int nwr = trow >> 5, jj = trow & 31, pgu = jj >> 4, cc = jj & 15;
    const long grow = brow0 + (pgu ? HIDDEN : 0) + n0 + nwr * 16 + cc;
    const __half* pB = g_wugh + grow * D_MODEL + tc16 * 8;

    #define ISSUE_UG(SIDX, K0) do { \
        uint32_t _s = smem_b + (uint32_t)(SIDX) * STAGE; \
        _Pragma("unroll") \
        for (int _it = 0; _it < 4; _it++) \
            CP_ASYNC16(_s + dA[_it], pA + (long)_it * 64 * D_MODEL + (K0)); \
        CP_ASYNC16(_s + 16384 + dB, pB + (K0)); \
    } while (0)

    float acc[4][4][4];
    #pragma unroll
    for (int i = 0; i < 4; i++)
        #pragma unroll
        for (int j = 0; j < 4; j++)
            #pragma unroll
            for (int k = 0; k < 4; k++) acc[i][j][k] = 0.0f;

    const int NPAIR = (D_MODEL / 32) / 2;   // 32 pairs

    ISSUE_UG(0, 0);
    ISSUE_UG(1, 32);
    CP_COMMIT();

    for (int p = 0; p < NPAIR; p++) {
        CP_WAIT0();
        __syncthreads();
        if (p + 1 < NPAIR) {
            ISSUE_UG((2 * p + 2) & 3, (long)(2 * p + 2) * 32);
            ISSUE_UG((2 * p + 3) & 3, (long)(2 * p + 3) * 32);
            CP_COMMIT();
        }
        compute_k32(smem_b + (uint32_t)((2 * p) & 3) * STAGE, acc, lane, mw, nw);
        compute_k32(smem_b + (uint32_t)((2 * p + 1) & 3) * STAGE, acc, lane, mw, nw);
    }
    #undef ISSUE_UG

    // epilogue: acc[mt][ntl] = gate (pr=0), acc[mt][2+ntl] = up (pr=1)
    #pragma unroll
    for (int mt = 0; mt < 4; mt++) {
        long row0 = arow0 + mw * 64 + mt * 16 + g;
        #pragma unroll
        for (int ntl = 0; ntl < 2; ntl++) {
            const float* ga = acc[mt][ntl];
            const float* ua = acc[mt][2 + ntl];
            int col = n0 + nw * 16 + ntl * 8 + tg * 2;
            __half2 v0(__float2half_rn(silu(ga[0]) * ua[0]),
                       __float2half_rn(silu(ga[1]) * ua[1]));
            __half2 v1(__float2half_rn(silu(ga[2]) * ua[2]),
                       __float2half_rn(silu(ga[3]) * ua[3]));
            *reinterpret_cast<__half2*>(g_hh + row0 * HIDDEN + col) = v0;
            *reinterpret_cast<__half2*>(g_hh + (row0 + 8) * HIDDEN + col) = v1;
        }
    }
}

// ---------------- kernel 2: out = h @ Wd^T ----------------
// CTA: 256 tokens x 64 out-cols; warp tile 64 x 32. Two chunks per barrier.
__global__ __launch_bounds__(256, 2)
void moe_down_kernel(float* __restrict__ out)
{
    extern __shared__ char smem[];
    const uint32_t smem_b = smem_u32(smem);

    const int tid = threadIdx.x;
    const int lane = tid & 31, warp = tid >> 5;
    const int g = lane >> 2, tg = lane & 3;
    const int nw = warp & 1, mw = warp >> 1;

    const int e = blockIdx.z;
    const int m0 = blockIdx.y * 256;
    const int n0 = blockIdx.x * 64;

    const long arow0 = (long)e * TPE + m0;

    const int trow = tid >> 2, tc16 = tid & 3;
    uint32_t dA[4];
    #pragma unroll
    for (int it = 0; it < 4; it++)
        dA[it] = SW64((uint32_t)((trow + it * 64) * 64 + tc16 * 16));
    const uint32_t dB = SW64((uint32_t)(trow * 64 + tc16 * 16));

    const __half* pA = g_hh + (arow0 + trow) * HIDDEN + tc16 * 8;
    const long browb = (long)(n0 + trow) * (NUM_EXPERTS * HIDDEN) + (long)e * HIDDEN;
    const __half* pB = g_wdh + browb + tc16 * 8;

    #define ISSUE_DN(SIDX, K0) do { \
        uint32_t _s = smem_b + (uint32_t)(SIDX) * STAGE; \
        _Pragma("unroll") \
        for (int _it = 0; _it < 4; _it++) \
            CP_ASYNC16(_s + dA[_it], pA + (long)_it * 64 * HIDDEN + (K0)); \
        CP_ASYNC16(_s + 16384 + dB, pB + (K0)); \
    } while (0)

    float acc[4][4][4];
    #pragma unroll
    for (int i = 0; i < 4; i++)
        #pragma unroll
        for (int j = 0; j < 4; j++)
            #pragma unroll
            for (int k = 0; k < 4; k++) acc[i][j][k] = 0.0f;

    const int NPAIR = (HIDDEN / 32) / 2;    // 16 pairs

    ISSUE_DN(0, 0);
    ISSUE_DN(1, 32);
    CP_COMMIT();

    for (int p = 0; p < NPAIR; p++) {
        CP_WAIT0();
        __syncthreads();
        if (p + 1 < NPAIR) {
            ISSUE_DN((2 * p + 2) & 3, (long)(2 * p + 2) * 32);
            ISSUE_DN((2 * p + 3) & 3, (long)(2 * p + 3) * 32);
            CP_COMMIT();
        }
        compute_k32(smem_b + (uint32_t)((2 * p) & 3) * STAGE, acc, lane, mw, nw);
        compute_k32(smem_b + (uint32_t)((2 * p + 1) & 3) * STAGE, acc, lane, mw, nw);
    }
    #undef ISSUE_DN

    #pragma unroll
    for (int mt = 0; mt < 4; mt++) {
        long row0 = arow0 + mw * 64 + mt * 16 + g;
        #pragma unroll
        for (int nt = 0; nt < 4; nt++) {
            int col = n0 + nw * 32 + (nt >> 1) * 16 + (nt & 1) * 8 + tg * 2;
            float2 v0, v1;
            v0.x = acc[mt][nt][0]; v0.y = acc[mt][nt][1];
            v1.x = acc[mt][nt][2]; v1.y = acc[mt][nt][3];
            *reinterpret_cast<float2*>(out + row0 * D_MODEL + col) = v0;
            *reinterpret_cast<float2*>(out + (row0 + 8) * D_MODEL + col) = v1;
        }
    }
}

// ---------------- launch ----------------
extern "C" void kernel_launch(void* const* d_in, const int* in_sizes, int n_in,
                              void* d_out, int out_size)
{
    const float* x        = (const float*)d_in[0];  // [16384, 2048]
    const float* w_upgate = (const float*)d_in[1];  // [E*2H, D]
    const float* w_down   = (const float*)d_in[2];  // [D, E*H]
    float* out = (float*)d_out;

    cudaFuncSetAttribute(moe_upgate_kernel,
                         cudaFuncAttributeMaxDynamicSharedMemorySize, SMEM_TOTAL);
    cudaFuncSetAttribute(moe_down_kernel,
                         cudaFuncAttributeMaxDynamicSharedMemorySize, SMEM_TOTAL);

    __half *xh, *ugh, *wdh;
    cudaGetSymbolAddress((void**)&xh,  g_xh);
    cudaGetSymbolAddress((void**)&ugh, g_wugh);
    cudaGetSymbolAddress((void**)&wdh, g_wdh);

    {
        long n4x  = (long)TOTAL_TOKENS * D_MODEL / 4;
        long n4ug = (long)2 * NUM_EXPERTS * HIDDEN * D_MODEL / 4;
        long n4wd = (long)D_MODEL * NUM_EXPERTS * HIDDEN / 4;
        split_h_kernel<<<2048, 256>>>((const float4*)x, (uint2*)xh, n4x);
        split_h_kernel<<<2048, 256>>>((const float4*)w_upgate, (uint2*)ugh, n4ug);
        split_h_kernel<<<2048, 256>>>((const float4*)w_down, (uint2*)wdh, n4wd);
    }

    {
        dim3 grid(HIDDEN / 32, TPE / 256, NUM_EXPERTS);   // (32,8,8)
        moe_upgate_kernel<<<grid, 256, SMEM_TOTAL>>>();
    }
    {
        dim3 grid(D_MODEL / 64, TPE / 256, NUM_EXPERTS);  // (32,8,8)
        moe_down_kernel<<<grid, 256, SMEM_TOTAL>>>(out);
    }
}